// round 8
// baseline (speedup 1.0000x reference)
#include <cuda_runtime.h>
#include <math.h>

#define NN    50000
#define EE    800000
#define CC    64
#define FE    16
#define NLAY  7
#define GG    512
#define NCLSV 10
#define EPSV  1e-5f

// ---------------- f32x2 packed helpers (used in MLP only) ----------------
__device__ __forceinline__ unsigned long long pk2(float lo, float hi) {
    unsigned long long r;
    asm("mov.b64 %0, {%1, %2};" : "=l"(r) : "f"(lo), "f"(hi));
    return r;
}
__device__ __forceinline__ void upk2(float& lo, float& hi, unsigned long long v) {
    asm("mov.b64 {%0, %1}, %2;" : "=f"(lo), "=f"(hi) : "l"(v));
}
__device__ __forceinline__ unsigned long long fma2(unsigned long long a,
                                                   unsigned long long b,
                                                   unsigned long long c) {
    unsigned long long d;
    asm("fma.rn.f32x2 %0, %1, %2, %3;" : "=l"(d) : "l"(a), "l"(b), "l"(c));
    return d;
}

// ---------------- static device scratch ----------------
__device__ float  g_w[NLAY * EE];
__device__ float  g_dis2[NN * 8];
__device__ int2   g_epk[NLAY * EE];
__device__ int    g_off[NN + 1];
__device__ int    g_cnt[NN];
__device__ int    g_cnt2[NN];
__device__ float  g_bufA[NN * CC];
__device__ float  g_bufB[NN * CC];
__device__ float  g_bufC[NN * CC];
__device__ float  g_bufD[NN * CC];
__device__ float  g_xl[NN * CC];
__device__ double g_bn[6 * 8 * 2 * CC];   // 6 slots x 8 spread copies x (sum64, sq64)
__device__ unsigned g_pool[GG * CC];

// ---------------- zero ----------------
__global__ void k_zero() {
    int i = blockIdx.x * blockDim.x + threadIdx.x;
    if (i < NN) { g_cnt[i] = 0; g_cnt2[i] = 0; }
    if (i < NN * 8) g_dis2[i] = 0.f;
    if (i < GG * CC) g_pool[i] = 0u;
    if (i < 6 * 8 * 2 * CC) g_bn[i] = 0.0;
}

// ---------------- edge MLPs: 4 edges/thread, f32x2, LDS.128 weight loads ----------------
struct MlpP { const float* w1; const float* b1; const float* w2; const float* b2; };
struct MlpAll { MlpP p[NLAY]; };

__global__ void __launch_bounds__(256) k_mlp(const float* __restrict__ ea,
                                             const int* __restrict__ col, MlpAll mp) {
    __shared__ __align__(16) float2 sw1[NLAY * FE * FE];
    __shared__ float  sb1[NLAY * FE];
    __shared__ float  sw2[NLAY * FE];
    __shared__ float  sb2[NLAY];
    int t = threadIdx.x;
    for (int i = t; i < NLAY * FE * FE; i += 256) {
        int l = i >> 8;
        float v = mp.p[l].w1[i & 255];
        sw1[i] = make_float2(v, v);
    }
    for (int i = t; i < NLAY * FE; i += 256) {
        int l = i >> 4;
        sb1[i] = mp.p[l].b1[i & 15];
        sw2[i] = mp.p[l].w2[i & 15];
    }
    if (t < NLAY) sb2[t] = mp.p[t].b2[0];
    __syncthreads();

    int e0 = (blockIdx.x * 256 + t) * 4;
    if (e0 >= EE) return;

    unsigned long long a01[FE], a23[FE];
    {
        float a[4][FE];
#pragma unroll
        for (int i = 0; i < 4; i++) {
            const float4* p4 = (const float4*)(ea + (size_t)(e0 + i) * FE);
#pragma unroll
            for (int q = 0; q < 4; q++) {
                float4 v = p4[q];
                a[i][4 * q] = v.x; a[i][4 * q + 1] = v.y;
                a[i][4 * q + 2] = v.z; a[i][4 * q + 3] = v.w;
            }
        }
#pragma unroll
        for (int k = 0; k < FE; k++) {
            a01[k] = pk2(a[0][k], a[1][k]);
            a23[k] = pk2(a[2][k], a[3][k]);
        }
    }
    int c0 = col[e0], c1 = col[e0 + 1], c2 = col[e0 + 2], c3 = col[e0 + 3];
    atomicAdd(&g_cnt[c0], 1); atomicAdd(&g_cnt[c1], 1);
    atomicAdd(&g_cnt[c2], 1); atomicAdd(&g_cnt[c3], 1);

#pragma unroll 1
    for (int l = 0; l < NLAY; l++) {
        const float2* w1l = sw1 + l * 256;
        const float*  b1l = sb1 + l * 16;
        const float*  w2l = sw2 + l * 16;
        float bias2 = sb2[l];
        float s0 = bias2, s1 = bias2, s2 = bias2, s3 = bias2;
#pragma unroll
        for (int j = 0; j < FE; j++) {
            float bj = b1l[j];
            unsigned long long h01 = pk2(bj, bj);
            unsigned long long h23 = h01;
            const ulonglong2* wrow = (const ulonglong2*)(w1l + j * 16);
#pragma unroll
            for (int k = 0; k < FE; k += 2) {
                ulonglong2 w = wrow[k >> 1];
                h01 = fma2(a01[k], w.x, h01);
                h23 = fma2(a23[k], w.x, h23);
                h01 = fma2(a01[k + 1], w.y, h01);
                h23 = fma2(a23[k + 1], w.y, h23);
            }
            float h0, h1, h2, h3;
            upk2(h0, h1, h01); upk2(h2, h3, h23);
            float w2j = w2l[j];
            s0 = fmaf(fmaxf(h0, 0.f), w2j, s0);
            s1 = fmaf(fmaxf(h1, 0.f), w2j, s1);
            s2 = fmaf(fmaxf(h2, 0.f), w2j, s2);
            s3 = fmaf(fmaxf(h3, 0.f), w2j, s3);
        }
        float w0 = __fdividef(1.f, 1.f + __expf(-s0));
        float w1 = __fdividef(1.f, 1.f + __expf(-s1));
        float w2v = __fdividef(1.f, 1.f + __expf(-s2));
        float w3 = __fdividef(1.f, 1.f + __expf(-s3));
        *(float4*)&g_w[(size_t)l * EE + e0] = make_float4(w0, w1, w2v, w3);
        atomicAdd(&g_dis2[c0 * 8 + l], w0);
        atomicAdd(&g_dis2[c1 * 8 + l], w1);
        atomicAdd(&g_dis2[c2 * 8 + l], w2v);
        atomicAdd(&g_dis2[c3 * 8 + l], w3);
    }
}

// ---------------- CSR offsets ----------------
__global__ void k_scan() {
    __shared__ int sums[1024];
    const int CH = (NN + 1023) / 1024;
    int t = threadIdx.x;
    int base = t * CH;
    int s = 0;
    for (int i = 0; i < CH; i++) {
        int idx = base + i;
        if (idx < NN) s += g_cnt[idx];
    }
    sums[t] = s;
    __syncthreads();
    for (int off = 1; off < 1024; off <<= 1) {
        int v = 0;
        if (t >= off) v = sums[t - off];
        __syncthreads();
        sums[t] += v;
        __syncthreads();
    }
    int excl = (t == 0) ? 0 : sums[t - 1];
    for (int i = 0; i < CH; i++) {
        int idx = base + i;
        if (idx < NN) {
            int c = g_cnt[idx];
            g_off[idx] = excl;
            excl += c;
        }
    }
    if (t == 1023) g_off[NN] = excl;
}

__global__ void k_dis() {
    int i = blockIdx.x * blockDim.x + threadIdx.x;
    if (i < NN * 8) g_dis2[i] = rsqrtf(g_dis2[i] + 1.0f);
}

// ---------------- CSR fill + gcn_norm ----------------
__global__ void k_fillnorm(const int* __restrict__ row, const int* __restrict__ col) {
    int e = blockIdx.x * blockDim.x + threadIdx.x;
    if (e >= EE) return;
    int r = row[e], c = col[e];
    int p = g_off[c] + atomicAdd(&g_cnt2[c], 1);
    float4 dr0 = *(const float4*)&g_dis2[r * 8];
    float4 dr1 = *(const float4*)&g_dis2[r * 8 + 4];
    float4 dc0 = *(const float4*)&g_dis2[c * 8];
    float4 dc1 = *(const float4*)&g_dis2[c * 8 + 4];
    float dr[7] = {dr0.x, dr0.y, dr0.z, dr0.w, dr1.x, dr1.y, dr1.z};
    float dc[7] = {dc0.x, dc0.y, dc0.z, dc0.w, dc1.x, dc1.y, dc1.z};
#pragma unroll
    for (int l = 0; l < NLAY; l++) {
        float w = g_w[(size_t)l * EE + e];
        g_epk[(size_t)l * EE + p] = make_int2(r, __float_as_int(dr[l] * w * dc[l]));
    }
}

// ---------------- node GEMM: 128x64 tile, 128 threads, 8x8 register tile ----------------
// Dynamic smem: sx[128][68] then swt[64][68]
#define SX_STRIDE  68
#define GEMM_SMEM  ((128 * SX_STRIDE + 64 * SX_STRIDE) * 4)

__global__ void __launch_bounds__(128) k_gemm(const float* __restrict__ x,
                                              const float* __restrict__ lw,
                                              float* __restrict__ out,
                                              const double* __restrict__ bns) {
    extern __shared__ __align__(16) float dsm[];
    float (*sx)[SX_STRIDE]  = (float(*)[SX_STRIDE])dsm;                      // [row][k]
    float (*swt)[SX_STRIDE] = (float(*)[SX_STRIDE])(dsm + 128 * SX_STRIDE);  // [k][c]
    __shared__ float smu[CC], sinv[CC];
    int t = threadIdx.x;
#pragma unroll
    for (int i = 0; i < 32; i++) {
        int e = i * 128 + t;
        int c = e & 63, k = e >> 6;
        swt[k][c] = lw[c * CC + k];
    }
    if (bns != nullptr && t < CC) {
        double s = 0.0, q = 0.0;
#pragma unroll
        for (int cp = 0; cp < 8; cp++) {
            s += bns[cp * 128 + t];
            q += bns[cp * 128 + 64 + t];
        }
        double mu = s * (1.0 / NN);
        double var = q * (1.0 / NN) - mu * mu;
        smu[t] = (float)mu;
        sinv[t] = rsqrtf((float)var + EPSV);
    }
    __syncthreads();
    int row0 = blockIdx.x * 128;
#pragma unroll
    for (int i = 0; i < 16; i++) {
        int idx = i * 128 + t;
        int r = idx >> 4, kq = (idx & 15) * 4;
        int gr = row0 + r;
        float4 v = (gr < NN) ? *(const float4*)&x[gr * CC + kq]
                             : make_float4(0.f, 0.f, 0.f, 0.f);
        if (bns != nullptr) {
            v.x = fmaxf((v.x - smu[kq + 0]) * sinv[kq + 0], 0.f);
            v.y = fmaxf((v.y - smu[kq + 1]) * sinv[kq + 1], 0.f);
            v.z = fmaxf((v.z - smu[kq + 2]) * sinv[kq + 2], 0.f);
            v.w = fmaxf((v.w - smu[kq + 3]) * sinv[kq + 3], 0.f);
        }
        *(float4*)&sx[r][kq] = v;
    }
    __syncthreads();

    int rg = (t >> 3) * 8;   // 8 rows
    int cg = (t & 7) * 8;    // 8 cols
    float acc[8][8];
#pragma unroll
    for (int i = 0; i < 8; i++)
#pragma unroll
        for (int j = 0; j < 8; j++) acc[i][j] = 0.f;

#pragma unroll 1
    for (int kb = 0; kb < CC; kb += 4) {
        float4 a[8];
#pragma unroll
        for (int i = 0; i < 8; i++) a[i] = *(const float4*)&sx[rg + i][kb];
        float4 b0[4], b1[4];
#pragma unroll
        for (int j = 0; j < 4; j++) {
            b0[j] = *(const float4*)&swt[kb + j][cg];
            b1[j] = *(const float4*)&swt[kb + j][cg + 4];
        }
#pragma unroll
        for (int i = 0; i < 8; i++) {
            float av[4] = {a[i].x, a[i].y, a[i].z, a[i].w};
#pragma unroll
            for (int j = 0; j < 4; j++) {
                acc[i][0] = fmaf(av[j], b0[j].x, acc[i][0]);
                acc[i][1] = fmaf(av[j], b0[j].y, acc[i][1]);
                acc[i][2] = fmaf(av[j], b0[j].z, acc[i][2]);
                acc[i][3] = fmaf(av[j], b0[j].w, acc[i][3]);
                acc[i][4] = fmaf(av[j], b1[j].x, acc[i][4]);
                acc[i][5] = fmaf(av[j], b1[j].y, acc[i][5]);
                acc[i][6] = fmaf(av[j], b1[j].z, acc[i][6]);
                acc[i][7] = fmaf(av[j], b1[j].w, acc[i][7]);
            }
        }
    }
#pragma unroll
    for (int i = 0; i < 8; i++) {
        int gr = row0 + rg + i;
        if (gr < NN) {
            *(float4*)&out[gr * CC + cg] =
                make_float4(acc[i][0], acc[i][1], acc[i][2], acc[i][3]);
            *(float4*)&out[gr * CC + cg + 4] =
                make_float4(acc[i][4], acc[i][5], acc[i][6], acc[i][7]);
        }
    }
}

// ---------------- message gather: 2 nodes/warp, float4 lanes, smem staging ----------------
// mode 0: out = acc; mode 1: out = acc + skipA; mode 2: pool relu(acc+skipA+skipB)
__global__ void __launch_bounds__(512) k_gather(
    int l, const float4* __restrict__ x4, float* __restrict__ out,
    const float* __restrict__ skipA, const float* __restrict__ skipB,
    const int* __restrict__ batch, int mode, int statslot)
{
    __shared__ __align__(16) int2 sed[16][2][16];
    __shared__ __align__(16) float ssum[32][64];
    __shared__ __align__(16) float ssq[32][64];
    int t = threadIdx.x;
    int w = t >> 5, lane = t & 31;
    int half = lane >> 4, sl = lane & 15;
    unsigned hm = half ? 0xFFFF0000u : 0x0000FFFFu;
    int node = blockIdx.x * 32 + w * 2 + half;
    bool valid = node < NN;

    float4 acc = make_float4(0.f, 0.f, 0.f, 0.f);
    if (valid) {
        float d = g_dis2[node * 8 + l];
        float dd = d * d;
        float4 self = x4[node * 16 + sl];
        acc.x = self.x * dd; acc.y = self.y * dd;
        acc.z = self.z * dd; acc.w = self.w * dd;

        int s0 = g_off[node], e0 = g_off[node + 1];
        const int2* ep = g_epk + (size_t)l * EE;
        for (int j0 = s0; j0 < e0; j0 += 16) {
            int idx = j0 + sl;
            int2 p = (idx < e0) ? ep[idx] : make_int2(0, 0);
            sed[w][half][sl] = p;
            __syncwarp(hm);
            int cnt = e0 - j0; if (cnt > 16) cnt = 16;
            int cntp = (cnt + 3) & ~3;
            for (int k = 0; k < cntp; k += 4) {
                int4 q0 = *(const int4*)&sed[w][half][k];
                int4 q1 = *(const int4*)&sed[w][half][k + 2];
                float4 v0 = x4[(size_t)q0.x * 16 + sl];
                float4 v1 = x4[(size_t)q0.z * 16 + sl];
                float4 v2 = x4[(size_t)q1.x * 16 + sl];
                float4 v3 = x4[(size_t)q1.z * 16 + sl];
                float n0 = __int_as_float(q0.y), n1 = __int_as_float(q0.w);
                float n2 = __int_as_float(q1.y), n3 = __int_as_float(q1.w);
                acc.x = fmaf(v0.x, n0, acc.x); acc.y = fmaf(v0.y, n0, acc.y);
                acc.z = fmaf(v0.z, n0, acc.z); acc.w = fmaf(v0.w, n0, acc.w);
                acc.x = fmaf(v1.x, n1, acc.x); acc.y = fmaf(v1.y, n1, acc.y);
                acc.z = fmaf(v1.z, n1, acc.z); acc.w = fmaf(v1.w, n1, acc.w);
                acc.x = fmaf(v2.x, n2, acc.x); acc.y = fmaf(v2.y, n2, acc.y);
                acc.z = fmaf(v2.z, n2, acc.z); acc.w = fmaf(v2.w, n2, acc.w);
                acc.x = fmaf(v3.x, n3, acc.x); acc.y = fmaf(v3.y, n3, acc.y);
                acc.z = fmaf(v3.z, n3, acc.z); acc.w = fmaf(v3.w, n3, acc.w);
            }
            __syncwarp(hm);
        }

        int base4 = node * 16 + sl;
        if (mode == 1) {
            float4 s = ((const float4*)skipA)[base4];
            acc.x += s.x; acc.y += s.y; acc.z += s.z; acc.w += s.w;
        }
        if (mode == 2) {
            float4 sA = ((const float4*)skipA)[base4];
            float4 sB = ((const float4*)skipB)[base4];
            acc.x = fmaxf(acc.x + sA.x + sB.x, 0.f);
            acc.y = fmaxf(acc.y + sA.y + sB.y, 0.f);
            acc.z = fmaxf(acc.z + sA.z + sB.z, 0.f);
            acc.w = fmaxf(acc.w + sA.w + sB.w, 0.f);
            int g = batch[node];
            atomicMax(&g_pool[g * CC + sl * 4 + 0], __float_as_uint(acc.x));
            atomicMax(&g_pool[g * CC + sl * 4 + 1], __float_as_uint(acc.y));
            atomicMax(&g_pool[g * CC + sl * 4 + 2], __float_as_uint(acc.z));
            atomicMax(&g_pool[g * CC + sl * 4 + 3], __float_as_uint(acc.w));
        } else {
            ((float4*)out)[base4] = acc;
        }
    }

    if (statslot >= 0) {
        int grp = w * 2 + half;
        *(float4*)&ssum[grp][sl * 4] = acc;
        *(float4*)&ssq[grp][sl * 4] =
            make_float4(acc.x * acc.x, acc.y * acc.y, acc.z * acc.z, acc.w * acc.w);
        __syncthreads();
        if (t < 64) {
            float s = 0.f, q = 0.f;
#pragma unroll
            for (int gg = 0; gg < 32; gg++) { s += ssum[gg][t]; q += ssq[gg][t]; }
            double* slot = g_bn + statslot * 1024 + (blockIdx.x & 7) * 128;
            atomicAdd(&slot[t], (double)s);
            atomicAdd(&slot[64 + t], (double)q);
        }
    }
}

// ---------------- final linear ----------------
__global__ void k_fin(const float* __restrict__ lw, const float* __restrict__ lb,
                      float* __restrict__ out) {
    __shared__ float sw[NCLSV * CC];
    __shared__ float sb[NCLSV];
    int t = threadIdx.x;
    for (int i = t; i < NCLSV * CC; i += blockDim.x) sw[i] = lw[i];
    if (t < NCLSV) sb[t] = lb[t];
    __syncthreads();
    int g = blockIdx.x * blockDim.x + t;
    if (g >= GG) return;
    float acc[NCLSV];
#pragma unroll
    for (int j = 0; j < NCLSV; j++) acc[j] = sb[j];
    for (int k = 0; k < CC; k++) {
        float p = __uint_as_float(g_pool[g * CC + k]);
#pragma unroll
        for (int j = 0; j < NCLSV; j++) acc[j] += p * sw[j * CC + k];
    }
#pragma unroll
    for (int j = 0; j < NCLSV; j++) out[g * NCLSV + j] = acc[j];
}

// ---------------- host launcher ----------------
extern "C" void kernel_launch(void* const* d_in, const int* in_sizes, int n_in,
                              void* d_out, int out_size) {
    const float* x      = (const float*)d_in[0];
    const int*   ei     = (const int*)d_in[1];
    const int*   batch  = (const int*)d_in[2];
    const float* ea     = (const float*)d_in[4];
    const float* c1_lw  = (const float*)d_in[5];
    const float* c1_w1  = (const float*)d_in[6];
    const float* c1_b1  = (const float*)d_in[7];
    const float* c1_w2  = (const float*)d_in[8];
    const float* c1_b2  = (const float*)d_in[9];
    const float* h1_lw  = (const float*)d_in[10];
    const float* h1_w1  = (const float*)d_in[11];
    const float* h1_b1  = (const float*)d_in[12];
    const float* h1_w2  = (const float*)d_in[13];
    const float* h1_b2  = (const float*)d_in[14];
    const float* h2_lw  = (const float*)d_in[15];
    const float* h2_w1  = (const float*)d_in[16];
    const float* h2_b1  = (const float*)d_in[17];
    const float* h2_w2  = (const float*)d_in[18];
    const float* h2_b2  = (const float*)d_in[19];
    const float* lin_w  = (const float*)d_in[20];
    const float* lin_b  = (const float*)d_in[21];

    const int* row = ei;
    const int* col = ei + EE;

    float *A, *B, *C, *D, *XL;
    double* BN;
    cudaGetSymbolAddress((void**)&A,  g_bufA);
    cudaGetSymbolAddress((void**)&B,  g_bufB);
    cudaGetSymbolAddress((void**)&C,  g_bufC);
    cudaGetSymbolAddress((void**)&D,  g_bufD);
    cudaGetSymbolAddress((void**)&XL, g_xl);
    cudaGetSymbolAddress((void**)&BN, g_bn);

    cudaFuncSetAttribute(k_gemm, cudaFuncAttributeMaxDynamicSharedMemorySize, GEMM_SMEM);

    const int EB  = (EE + 255) / 256;             // 3125
    const int EB4 = (EE / 4 + 255) / 256;         // 782
    const int ZB  = (NN * 8 + 255) / 256;         // 1563

    MlpAll mp;
    mp.p[0] = {c1_w1, c1_b1, c1_w2, c1_b2};
    for (int i = 0; i < 3; i++) {
        mp.p[1 + i] = {h1_w1 + i * FE * FE, h1_b1 + i * FE, h1_w2 + i * FE, h1_b2 + i};
        mp.p[4 + i] = {h2_w1 + i * FE * FE, h2_b1 + i * FE, h2_w2 + i * FE, h2_b2 + i};
    }

    const int GEMM_B = (NN + 127) / 128;  // 391
    const int GATH_B = (NN + 31) / 32;    // 1563

    k_zero<<<ZB, 256>>>();                                       // 0
    k_mlp<<<EB4, 256>>>(ea, col, mp);                            // 1
    k_scan<<<1, 1024>>>();                                       // 2
    k_gemm<<<GEMM_B, 128, GEMM_SMEM>>>(x, c1_lw, XL, nullptr);   // 3  <- profiled slot
    k_dis<<<ZB, 256>>>();                                        // 4
    k_fillnorm<<<EB, 256>>>(row, col);                           // 5

    k_gather<<<GATH_B, 512>>>(0, (const float4*)XL, A, nullptr, nullptr, nullptr, 0, 0);
    k_gemm<<<GEMM_B, 128, GEMM_SMEM>>>(A, h1_lw + 0 * CC * CC, XL, BN + 0 * 1024);
    k_gather<<<GATH_B, 512>>>(1, (const float4*)XL, B, nullptr, nullptr, nullptr, 0, 1);
    k_gemm<<<GEMM_B, 128, GEMM_SMEM>>>(B, h1_lw + 1 * CC * CC, XL, BN + 1 * 1024);
    k_gather<<<GATH_B, 512>>>(2, (const float4*)XL, C, nullptr, nullptr, nullptr, 0, 2);
    k_gemm<<<GEMM_B, 128, GEMM_SMEM>>>(C, h1_lw + 2 * CC * CC, XL, BN + 2 * 1024);
    k_gather<<<GATH_B, 512>>>(3, (const float4*)XL, D, A, nullptr, nullptr, 1, 3);   // D = x1
    k_gemm<<<GEMM_B, 128, GEMM_SMEM>>>(D, h2_lw + 0 * CC * CC, XL, BN + 3 * 1024);
    k_gather<<<GATH_B, 512>>>(4, (const float4*)XL, B, nullptr, nullptr, nullptr, 0, 4);
    k_gemm<<<GEMM_B, 128, GEMM_SMEM>>>(B, h2_lw + 1 * CC * CC, XL, BN + 4 * 1024);
    k_gather<<<GATH_B, 512>>>(5, (const float4*)XL, C, nullptr, nullptr, nullptr, 0, 5);
    k_gemm<<<GEMM_B, 128, GEMM_SMEM>>>(C, h2_lw + 2 * CC * CC, XL, BN + 5 * 1024);
    k_gather<<<GATH_B, 512>>>(6, (const float4*)XL, nullptr, A, D, batch, 2, -1);    // pool
    k_fin<<<2, 256>>>(lin_w, lin_b, (float*)d_out);
}

// round 9
// speedup vs baseline: 1.1174x; 1.1174x over previous
#include <cuda_runtime.h>
#include <math.h>

#define NN    50000
#define EE    800000
#define CC    64
#define FE    16
#define NLAY  7
#define GG    512
#define NCLSV 10
#define EPSV  1e-5f

// ---------------- f32x2 packed helpers (used in MLP only) ----------------
__device__ __forceinline__ unsigned long long pk2(float lo, float hi) {
    unsigned long long r;
    asm("mov.b64 %0, {%1, %2};" : "=l"(r) : "f"(lo), "f"(hi));
    return r;
}
__device__ __forceinline__ void upk2(float& lo, float& hi, unsigned long long v) {
    asm("mov.b64 {%0, %1}, %2;" : "=f"(lo), "=f"(hi) : "l"(v));
}
__device__ __forceinline__ unsigned long long fma2(unsigned long long a,
                                                   unsigned long long b,
                                                   unsigned long long c) {
    unsigned long long d;
    asm("fma.rn.f32x2 %0, %1, %2, %3;" : "=l"(d) : "l"(a), "l"(b), "l"(c));
    return d;
}

// ---------------- static device scratch ----------------
__device__ float  g_w[NLAY * EE];
__device__ float  g_dis2[NN * 8];
__device__ int2   g_epk[NLAY * EE];
__device__ int    g_off[NN + 1];
__device__ int    g_cnt[NN];
__device__ int    g_cnt2[NN];
__device__ float  g_bufA[NN * CC];
__device__ float  g_bufB[NN * CC];
__device__ float  g_bufC[NN * CC];
__device__ float  g_bufD[NN * CC];
__device__ float  g_xl[NN * CC];
__device__ double g_bn[6 * 8 * 2 * CC];   // 6 slots x 8 spread copies x (sum64, sq64)
__device__ unsigned g_pool[GG * CC];

// ---------------- zero ----------------
__global__ void k_zero() {
    int i = blockIdx.x * blockDim.x + threadIdx.x;
    if (i < NN) { g_cnt[i] = 0; g_cnt2[i] = 0; }
    if (i < NN * 8) g_dis2[i] = 0.f;
    if (i < GG * CC) g_pool[i] = 0u;
    if (i < 6 * 8 * 2 * CC) g_bn[i] = 0.0;
}

// ---------------- edge MLPs: 4 edges/thread, f32x2, LDS.128 weight loads ----------------
struct MlpP { const float* w1; const float* b1; const float* w2; const float* b2; };
struct MlpAll { MlpP p[NLAY]; };

__global__ void __launch_bounds__(256) k_mlp(const float* __restrict__ ea,
                                             const int* __restrict__ col, MlpAll mp) {
    __shared__ __align__(16) float2 sw1[NLAY * FE * FE];
    __shared__ float  sb1[NLAY * FE];
    __shared__ float  sw2[NLAY * FE];
    __shared__ float  sb2[NLAY];
    int t = threadIdx.x;
    for (int i = t; i < NLAY * FE * FE; i += 256) {
        int l = i >> 8;
        float v = mp.p[l].w1[i & 255];
        sw1[i] = make_float2(v, v);
    }
    for (int i = t; i < NLAY * FE; i += 256) {
        int l = i >> 4;
        sb1[i] = mp.p[l].b1[i & 15];
        sw2[i] = mp.p[l].w2[i & 15];
    }
    if (t < NLAY) sb2[t] = mp.p[t].b2[0];
    __syncthreads();

    int e0 = (blockIdx.x * 256 + t) * 4;
    if (e0 >= EE) return;

    unsigned long long a01[FE], a23[FE];
    {
        float a[4][FE];
#pragma unroll
        for (int i = 0; i < 4; i++) {
            const float4* p4 = (const float4*)(ea + (size_t)(e0 + i) * FE);
#pragma unroll
            for (int q = 0; q < 4; q++) {
                float4 v = p4[q];
                a[i][4 * q] = v.x; a[i][4 * q + 1] = v.y;
                a[i][4 * q + 2] = v.z; a[i][4 * q + 3] = v.w;
            }
        }
#pragma unroll
        for (int k = 0; k < FE; k++) {
            a01[k] = pk2(a[0][k], a[1][k]);
            a23[k] = pk2(a[2][k], a[3][k]);
        }
    }
    int c0 = col[e0], c1 = col[e0 + 1], c2 = col[e0 + 2], c3 = col[e0 + 3];
    atomicAdd(&g_cnt[c0], 1); atomicAdd(&g_cnt[c1], 1);
    atomicAdd(&g_cnt[c2], 1); atomicAdd(&g_cnt[c3], 1);

#pragma unroll 1
    for (int l = 0; l < NLAY; l++) {
        const float2* w1l = sw1 + l * 256;
        const float*  b1l = sb1 + l * 16;
        const float*  w2l = sw2 + l * 16;
        float bias2 = sb2[l];
        float s0 = bias2, s1 = bias2, s2 = bias2, s3 = bias2;
#pragma unroll
        for (int j = 0; j < FE; j++) {
            float bj = b1l[j];
            unsigned long long h01 = pk2(bj, bj);
            unsigned long long h23 = h01;
            const ulonglong2* wrow = (const ulonglong2*)(w1l + j * 16);
#pragma unroll
            for (int k = 0; k < FE; k += 2) {
                ulonglong2 w = wrow[k >> 1];
                h01 = fma2(a01[k], w.x, h01);
                h23 = fma2(a23[k], w.x, h23);
                h01 = fma2(a01[k + 1], w.y, h01);
                h23 = fma2(a23[k + 1], w.y, h23);
            }
            float h0, h1, h2, h3;
            upk2(h0, h1, h01); upk2(h2, h3, h23);
            float w2j = w2l[j];
            s0 = fmaf(fmaxf(h0, 0.f), w2j, s0);
            s1 = fmaf(fmaxf(h1, 0.f), w2j, s1);
            s2 = fmaf(fmaxf(h2, 0.f), w2j, s2);
            s3 = fmaf(fmaxf(h3, 0.f), w2j, s3);
        }
        float w0 = __fdividef(1.f, 1.f + __expf(-s0));
        float w1 = __fdividef(1.f, 1.f + __expf(-s1));
        float w2v = __fdividef(1.f, 1.f + __expf(-s2));
        float w3 = __fdividef(1.f, 1.f + __expf(-s3));
        *(float4*)&g_w[(size_t)l * EE + e0] = make_float4(w0, w1, w2v, w3);
        atomicAdd(&g_dis2[c0 * 8 + l], w0);
        atomicAdd(&g_dis2[c1 * 8 + l], w1);
        atomicAdd(&g_dis2[c2 * 8 + l], w2v);
        atomicAdd(&g_dis2[c3 * 8 + l], w3);
    }
}

// ---------------- CSR offsets ----------------
__global__ void k_scan() {
    __shared__ int sums[1024];
    const int CH = (NN + 1023) / 1024;
    int t = threadIdx.x;
    int base = t * CH;
    int s = 0;
    for (int i = 0; i < CH; i++) {
        int idx = base + i;
        if (idx < NN) s += g_cnt[idx];
    }
    sums[t] = s;
    __syncthreads();
    for (int off = 1; off < 1024; off <<= 1) {
        int v = 0;
        if (t >= off) v = sums[t - off];
        __syncthreads();
        sums[t] += v;
        __syncthreads();
    }
    int excl = (t == 0) ? 0 : sums[t - 1];
    for (int i = 0; i < CH; i++) {
        int idx = base + i;
        if (idx < NN) {
            int c = g_cnt[idx];
            g_off[idx] = excl;
            excl += c;
        }
    }
    if (t == 1023) g_off[NN] = excl;
}

__global__ void k_dis() {
    int i = blockIdx.x * blockDim.x + threadIdx.x;
    if (i < NN * 8) g_dis2[i] = rsqrtf(g_dis2[i] + 1.0f);
}

// ---------------- CSR fill + gcn_norm ----------------
__global__ void k_fillnorm(const int* __restrict__ row, const int* __restrict__ col) {
    int e = blockIdx.x * blockDim.x + threadIdx.x;
    if (e >= EE) return;
    int r = row[e], c = col[e];
    int p = g_off[c] + atomicAdd(&g_cnt2[c], 1);
    float4 dr0 = *(const float4*)&g_dis2[r * 8];
    float4 dr1 = *(const float4*)&g_dis2[r * 8 + 4];
    float4 dc0 = *(const float4*)&g_dis2[c * 8];
    float4 dc1 = *(const float4*)&g_dis2[c * 8 + 4];
    float dr[7] = {dr0.x, dr0.y, dr0.z, dr0.w, dr1.x, dr1.y, dr1.z};
    float dc[7] = {dc0.x, dc0.y, dc0.z, dc0.w, dc1.x, dc1.y, dc1.z};
#pragma unroll
    for (int l = 0; l < NLAY; l++) {
        float w = g_w[(size_t)l * EE + e];
        g_epk[(size_t)l * EE + p] = make_int2(r, __float_as_int(dr[l] * w * dc[l]));
    }
}

// ---------------- node GEMM: 128x64 tile, 128 threads, 8x8 register tile ----------------
// Conflict-free mapping: rows rg+16i (warp row-groups -> distinct banks),
// cols cg*4 + {0..3} and cg*4 + 32 + {0..3} (8 distinct banks).
#define SX_STRIDE  68
#define GEMM_SMEM  ((128 * SX_STRIDE + 64 * SX_STRIDE) * 4)

__global__ void __launch_bounds__(128) k_gemm(const float* __restrict__ x,
                                              const float* __restrict__ lw,
                                              float* __restrict__ out,
                                              const double* __restrict__ bns) {
    extern __shared__ __align__(16) float dsm[];
    float (*sx)[SX_STRIDE]  = (float(*)[SX_STRIDE])dsm;                      // [row][k]
    float (*swt)[SX_STRIDE] = (float(*)[SX_STRIDE])(dsm + 128 * SX_STRIDE);  // [k][c]
    __shared__ float smu[CC], sinv[CC];
    int t = threadIdx.x;
    // coalesced weight read, transpose into smem: swt[k][c] = lw[c][k]
#pragma unroll
    for (int i = 0; i < 32; i++) {
        int e = i * 128 + t;
        int c = e >> 6, k = e & 63;
        swt[k][c] = lw[e];
    }
    if (bns != nullptr && t < CC) {
        double s = 0.0, q = 0.0;
#pragma unroll
        for (int cp = 0; cp < 8; cp++) {
            s += bns[cp * 128 + t];
            q += bns[cp * 128 + 64 + t];
        }
        double mu = s * (1.0 / NN);
        double var = q * (1.0 / NN) - mu * mu;
        smu[t] = (float)mu;
        sinv[t] = rsqrtf((float)var + EPSV);
    }
    __syncthreads();
    int row0 = blockIdx.x * 128;
#pragma unroll
    for (int i = 0; i < 16; i++) {
        int idx = i * 128 + t;
        int r = idx >> 4, kq = (idx & 15) * 4;
        int gr = row0 + r;
        float4 v = (gr < NN) ? *(const float4*)&x[gr * CC + kq]
                             : make_float4(0.f, 0.f, 0.f, 0.f);
        if (bns != nullptr) {
            v.x = fmaxf((v.x - smu[kq + 0]) * sinv[kq + 0], 0.f);
            v.y = fmaxf((v.y - smu[kq + 1]) * sinv[kq + 1], 0.f);
            v.z = fmaxf((v.z - smu[kq + 2]) * sinv[kq + 2], 0.f);
            v.w = fmaxf((v.w - smu[kq + 3]) * sinv[kq + 3], 0.f);
        }
        *(float4*)&sx[r][kq] = v;
    }
    __syncthreads();

    int rg = t >> 3;          // rows rg + 16*i, i = 0..7
    int cg = (t & 7) * 4;     // cols cg..cg+3 and cg+32..cg+35
    float acc[8][8];
#pragma unroll
    for (int i = 0; i < 8; i++)
#pragma unroll
        for (int j = 0; j < 8; j++) acc[i][j] = 0.f;

#pragma unroll 1
    for (int kb = 0; kb < CC; kb += 4) {
        float4 a[8];
#pragma unroll
        for (int i = 0; i < 8; i++) a[i] = *(const float4*)&sx[rg + 16 * i][kb];
        float4 b0[4], b1[4];
#pragma unroll
        for (int j = 0; j < 4; j++) {
            b0[j] = *(const float4*)&swt[kb + j][cg];
            b1[j] = *(const float4*)&swt[kb + j][cg + 32];
        }
#pragma unroll
        for (int i = 0; i < 8; i++) {
            float av[4] = {a[i].x, a[i].y, a[i].z, a[i].w};
#pragma unroll
            for (int j = 0; j < 4; j++) {
                acc[i][0] = fmaf(av[j], b0[j].x, acc[i][0]);
                acc[i][1] = fmaf(av[j], b0[j].y, acc[i][1]);
                acc[i][2] = fmaf(av[j], b0[j].z, acc[i][2]);
                acc[i][3] = fmaf(av[j], b0[j].w, acc[i][3]);
                acc[i][4] = fmaf(av[j], b1[j].x, acc[i][4]);
                acc[i][5] = fmaf(av[j], b1[j].y, acc[i][5]);
                acc[i][6] = fmaf(av[j], b1[j].z, acc[i][6]);
                acc[i][7] = fmaf(av[j], b1[j].w, acc[i][7]);
            }
        }
    }
#pragma unroll
    for (int i = 0; i < 8; i++) {
        int gr = row0 + rg + 16 * i;
        if (gr < NN) {
            *(float4*)&out[gr * CC + cg] =
                make_float4(acc[i][0], acc[i][1], acc[i][2], acc[i][3]);
            *(float4*)&out[gr * CC + cg + 32] =
                make_float4(acc[i][4], acc[i][5], acc[i][6], acc[i][7]);
        }
    }
}

// ---------------- message gather: warp/node, smem staging, 8-deep pipeline ----------------
// mode 0: out = acc; mode 1: out = acc + skipA; mode 2: pool relu(acc+skipA+skipB)
__global__ void __launch_bounds__(512) k_gather(
    int l, const float2* __restrict__ x2, float* __restrict__ out,
    const float* __restrict__ skipA, const float* __restrict__ skipB,
    const int* __restrict__ batch, int mode, int statslot)
{
    __shared__ __align__(16) int2 sed[16][32];
    __shared__ float ssum[16][64];
    __shared__ float ssq[16][64];
    int t = threadIdx.x;
    int w = t >> 5, lane = t & 31;
    int node = blockIdx.x * 16 + w;

    float d = g_dis2[node * 8 + l];
    float dd = d * d;
    float2 self = x2[node * 32 + lane];
    float ax = self.x * dd, ay = self.y * dd;

    int s0 = g_off[node], e0 = g_off[node + 1];
    const int2* ep = g_epk + (size_t)l * EE;
    for (int j0 = s0; j0 < e0; j0 += 32) {
        int idx = j0 + lane;
        int2 p = (idx < e0) ? ep[idx] : make_int2(0, 0);
        sed[w][lane] = p;
        __syncwarp();
        int cnt = e0 - j0; if (cnt > 32) cnt = 32;
        int cntp = (cnt + 7) & ~7;
        for (int k = 0; k < cntp; k += 8) {
            int4 q0 = *(const int4*)&sed[w][k];
            int4 q1 = *(const int4*)&sed[w][k + 2];
            int4 q2 = *(const int4*)&sed[w][k + 4];
            int4 q3 = *(const int4*)&sed[w][k + 6];
            float2 v0 = x2[(size_t)q0.x * 32 + lane];
            float2 v1 = x2[(size_t)q0.z * 32 + lane];
            float2 v2 = x2[(size_t)q1.x * 32 + lane];
            float2 v3 = x2[(size_t)q1.z * 32 + lane];
            float2 v4 = x2[(size_t)q2.x * 32 + lane];
            float2 v5 = x2[(size_t)q2.z * 32 + lane];
            float2 v6 = x2[(size_t)q3.x * 32 + lane];
            float2 v7 = x2[(size_t)q3.z * 32 + lane];
            float n0 = __int_as_float(q0.y), n1 = __int_as_float(q0.w);
            float n2 = __int_as_float(q1.y), n3 = __int_as_float(q1.w);
            float n4 = __int_as_float(q2.y), n5 = __int_as_float(q2.w);
            float n6 = __int_as_float(q3.y), n7 = __int_as_float(q3.w);
            ax = fmaf(v0.x, n0, ax); ay = fmaf(v0.y, n0, ay);
            ax = fmaf(v1.x, n1, ax); ay = fmaf(v1.y, n1, ay);
            ax = fmaf(v2.x, n2, ax); ay = fmaf(v2.y, n2, ay);
            ax = fmaf(v3.x, n3, ax); ay = fmaf(v3.y, n3, ay);
            ax = fmaf(v4.x, n4, ax); ay = fmaf(v4.y, n4, ay);
            ax = fmaf(v5.x, n5, ax); ay = fmaf(v5.y, n5, ay);
            ax = fmaf(v6.x, n6, ax); ay = fmaf(v6.y, n6, ay);
            ax = fmaf(v7.x, n7, ax); ay = fmaf(v7.y, n7, ay);
        }
        __syncwarp();
    }

    int base = node * 64 + lane * 2;
    float vx = ax, vy = ay;
    if (mode == 1) { vx += skipA[base]; vy += skipA[base + 1]; }
    if (mode == 2) {
        vx = fmaxf(ax + skipA[base] + skipB[base], 0.f);
        vy = fmaxf(ay + skipA[base + 1] + skipB[base + 1], 0.f);
        int g = batch[node];
        atomicMax(&g_pool[g * CC + lane * 2], __float_as_uint(vx));
        atomicMax(&g_pool[g * CC + lane * 2 + 1], __float_as_uint(vy));
    } else {
        float2 o; o.x = vx; o.y = vy;
        ((float2*)out)[node * 32 + lane] = o;
    }

    if (statslot >= 0) {
        ssum[w][lane * 2] = vx; ssum[w][lane * 2 + 1] = vy;
        ssq[w][lane * 2] = vx * vx; ssq[w][lane * 2 + 1] = vy * vy;
        __syncthreads();
        if (t < 64) {
            float s = 0.f, q = 0.f;
#pragma unroll
            for (int ww = 0; ww < 16; ww++) { s += ssum[ww][t]; q += ssq[ww][t]; }
            double* slot = g_bn + statslot * 1024 + (blockIdx.x & 7) * 128;
            atomicAdd(&slot[t], (double)s);
            atomicAdd(&slot[64 + t], (double)q);
        }
    }
}

// ---------------- final linear ----------------
__global__ void k_fin(const float* __restrict__ lw, const float* __restrict__ lb,
                      float* __restrict__ out) {
    __shared__ float sw[NCLSV * CC];
    __shared__ float sb[NCLSV];
    int t = threadIdx.x;
    for (int i = t; i < NCLSV * CC; i += blockDim.x) sw[i] = lw[i];
    if (t < NCLSV) sb[t] = lb[t];
    __syncthreads();
    int g = blockIdx.x * blockDim.x + t;
    if (g >= GG) return;
    float acc[NCLSV];
#pragma unroll
    for (int j = 0; j < NCLSV; j++) acc[j] = sb[j];
    for (int k = 0; k < CC; k++) {
        float p = __uint_as_float(g_pool[g * CC + k]);
#pragma unroll
        for (int j = 0; j < NCLSV; j++) acc[j] += p * sw[j * CC + k];
    }
#pragma unroll
    for (int j = 0; j < NCLSV; j++) out[g * NCLSV + j] = acc[j];
}

// ---------------- host launcher ----------------
extern "C" void kernel_launch(void* const* d_in, const int* in_sizes, int n_in,
                              void* d_out, int out_size) {
    const float* x      = (const float*)d_in[0];
    const int*   ei     = (const int*)d_in[1];
    const int*   batch  = (const int*)d_in[2];
    const float* ea     = (const float*)d_in[4];
    const float* c1_lw  = (const float*)d_in[5];
    const float* c1_w1  = (const float*)d_in[6];
    const float* c1_b1  = (const float*)d_in[7];
    const float* c1_w2  = (const float*)d_in[8];
    const float* c1_b2  = (const float*)d_in[9];
    const float* h1_lw  = (const float*)d_in[10];
    const float* h1_w1  = (const float*)d_in[11];
    const float* h1_b1  = (const float*)d_in[12];
    const float* h1_w2  = (const float*)d_in[13];
    const float* h1_b2  = (const float*)d_in[14];
    const float* h2_lw  = (const float*)d_in[15];
    const float* h2_w1  = (const float*)d_in[16];
    const float* h2_b1  = (const float*)d_in[17];
    const float* h2_w2  = (const float*)d_in[18];
    const float* h2_b2  = (const float*)d_in[19];
    const float* lin_w  = (const float*)d_in[20];
    const float* lin_b  = (const float*)d_in[21];

    const int* row = ei;
    const int* col = ei + EE;

    float *A, *B, *C, *D, *XL;
    double* BN;
    cudaGetSymbolAddress((void**)&A,  g_bufA);
    cudaGetSymbolAddress((void**)&B,  g_bufB);
    cudaGetSymbolAddress((void**)&C,  g_bufC);
    cudaGetSymbolAddress((void**)&D,  g_bufD);
    cudaGetSymbolAddress((void**)&XL, g_xl);
    cudaGetSymbolAddress((void**)&BN, g_bn);

    cudaFuncSetAttribute(k_gemm, cudaFuncAttributeMaxDynamicSharedMemorySize, GEMM_SMEM);

    const int EB  = (EE + 255) / 256;             // 3125
    const int EB4 = (EE / 4 + 255) / 256;         // 782
    const int ZB  = (NN * 8 + 255) / 256;         // 1563

    MlpAll mp;
    mp.p[0] = {c1_w1, c1_b1, c1_w2, c1_b2};
    for (int i = 0; i < 3; i++) {
        mp.p[1 + i] = {h1_w1 + i * FE * FE, h1_b1 + i * FE, h1_w2 + i * FE, h1_b2 + i};
        mp.p[4 + i] = {h2_w1 + i * FE * FE, h2_b1 + i * FE, h2_w2 + i * FE, h2_b2 + i};
    }

    const int GEMM_B = (NN + 127) / 128;  // 391
    const int GATH_B = NN / 16;           // 3125

    k_zero<<<ZB, 256>>>();                                       // 0
    k_mlp<<<EB4, 256>>>(ea, col, mp);                            // 1
    k_scan<<<1, 1024>>>();                                       // 2
    k_gemm<<<GEMM_B, 128, GEMM_SMEM>>>(x, c1_lw, XL, nullptr);   // 3  <- profiled slot
    k_dis<<<ZB, 256>>>();                                        // 4
    k_fillnorm<<<EB, 256>>>(row, col);                           // 5

    k_gather<<<GATH_B, 512>>>(0, (const float2*)XL, A, nullptr, nullptr, nullptr, 0, 0);
    k_gemm<<<GEMM_B, 128, GEMM_SMEM>>>(A, h1_lw + 0 * CC * CC, XL, BN + 0 * 1024);
    k_gather<<<GATH_B, 512>>>(1, (const float2*)XL, B, nullptr, nullptr, nullptr, 0, 1);
    k_gemm<<<GEMM_B, 128, GEMM_SMEM>>>(B, h1_lw + 1 * CC * CC, XL, BN + 1 * 1024);
    k_gather<<<GATH_B, 512>>>(2, (const float2*)XL, C, nullptr, nullptr, nullptr, 0, 2);
    k_gemm<<<GEMM_B, 128, GEMM_SMEM>>>(C, h1_lw + 2 * CC * CC, XL, BN + 2 * 1024);
    k_gather<<<GATH_B, 512>>>(3, (const float2*)XL, D, A, nullptr, nullptr, 1, 3);   // D = x1
    k_gemm<<<GEMM_B, 128, GEMM_SMEM>>>(D, h2_lw + 0 * CC * CC, XL, BN + 3 * 1024);
    k_gather<<<GATH_B, 512>>>(4, (const float2*)XL, B, nullptr, nullptr, nullptr, 0, 4);
    k_gemm<<<GEMM_B, 128, GEMM_SMEM>>>(B, h2_lw + 1 * CC * CC, XL, BN + 4 * 1024);
    k_gather<<<GATH_B, 512>>>(5, (const float2*)XL, C, nullptr, nullptr, nullptr, 0, 5);
    k_gemm<<<GEMM_B, 128, GEMM_SMEM>>>(C, h2_lw + 2 * CC * CC, XL, BN + 5 * 1024);
    k_gather<<<GATH_B, 512>>>(6, (const float2*)XL, nullptr, A, D, batch, 2, -1);    // pool
    k_fin<<<2, 256>>>(lin_w, lin_b, (float*)d_out);
}

// round 10
// speedup vs baseline: 1.1268x; 1.0084x over previous
#include <cuda_runtime.h>
#include <cuda_fp16.h>
#include <math.h>

#define NN    50000
#define EE    800000
#define CC    64
#define FE    16
#define NLAY  7
#define GG    512
#define NCLSV 10
#define EPSV  1e-5f

// ---------------- f32x2 packed helpers (used in MLP only) ----------------
__device__ __forceinline__ unsigned long long pk2(float lo, float hi) {
    unsigned long long r;
    asm("mov.b64 %0, {%1, %2};" : "=l"(r) : "f"(lo), "f"(hi));
    return r;
}
__device__ __forceinline__ void upk2(float& lo, float& hi, unsigned long long v) {
    asm("mov.b64 {%0, %1}, %2;" : "=f"(lo), "=f"(hi) : "l"(v));
}
__device__ __forceinline__ unsigned long long fma2(unsigned long long a,
                                                   unsigned long long b,
                                                   unsigned long long c) {
    unsigned long long d;
    asm("fma.rn.f32x2 %0, %1, %2, %3;" : "=l"(d) : "l"(a), "l"(b), "l"(c));
    return d;
}

// ---------------- static device scratch ----------------
__device__ float  g_w[NLAY * EE];
__device__ float  g_dis2[NN * 8];
__device__ int2   g_epk[NLAY * EE];
__device__ int    g_off[NN + 1];
__device__ int    g_cnt[NN];
__device__ int    g_cnt2[NN];
__device__ float  g_bufA[NN * CC];
__device__ float  g_bufB[NN * CC];
__device__ float  g_bufC[NN * CC];
__device__ float  g_bufD[NN * CC];
__device__ __half g_xlh[NN * CC];         // fp16 gather operand
__device__ double g_bn[6 * 8 * 2 * CC];   // 6 slots x 8 spread copies x (sum64, sq64)
__device__ unsigned g_pool[GG * CC];

// ---------------- zero ----------------
__global__ void k_zero() {
    int i = blockIdx.x * blockDim.x + threadIdx.x;
    if (i < NN) { g_cnt[i] = 0; g_cnt2[i] = 0; }
    if (i < NN * 8) g_dis2[i] = 0.f;
    if (i < GG * CC) g_pool[i] = 0u;
    if (i < 6 * 8 * 2 * CC) g_bn[i] = 0.0;
}

// ---------------- edge MLPs: 4 edges/thread, f32x2, LDS.128 weight loads ----------------
struct MlpP { const float* w1; const float* b1; const float* w2; const float* b2; };
struct MlpAll { MlpP p[NLAY]; };

__global__ void __launch_bounds__(256) k_mlp(const float* __restrict__ ea,
                                             const int* __restrict__ col, MlpAll mp) {
    __shared__ __align__(16) float2 sw1[NLAY * FE * FE];
    __shared__ float  sb1[NLAY * FE];
    __shared__ float  sw2[NLAY * FE];
    __shared__ float  sb2[NLAY];
    int t = threadIdx.x;
    for (int i = t; i < NLAY * FE * FE; i += 256) {
        int l = i >> 8;
        float v = mp.p[l].w1[i & 255];
        sw1[i] = make_float2(v, v);
    }
    for (int i = t; i < NLAY * FE; i += 256) {
        int l = i >> 4;
        sb1[i] = mp.p[l].b1[i & 15];
        sw2[i] = mp.p[l].w2[i & 15];
    }
    if (t < NLAY) sb2[t] = mp.p[t].b2[0];
    __syncthreads();

    int e0 = (blockIdx.x * 256 + t) * 4;
    if (e0 >= EE) return;

    unsigned long long a01[FE], a23[FE];
    {
        float a[4][FE];
#pragma unroll
        for (int i = 0; i < 4; i++) {
            const float4* p4 = (const float4*)(ea + (size_t)(e0 + i) * FE);
#pragma unroll
            for (int q = 0; q < 4; q++) {
                float4 v = p4[q];
                a[i][4 * q] = v.x; a[i][4 * q + 1] = v.y;
                a[i][4 * q + 2] = v.z; a[i][4 * q + 3] = v.w;
            }
        }
#pragma unroll
        for (int k = 0; k < FE; k++) {
            a01[k] = pk2(a[0][k], a[1][k]);
            a23[k] = pk2(a[2][k], a[3][k]);
        }
    }
    int c0 = col[e0], c1 = col[e0 + 1], c2 = col[e0 + 2], c3 = col[e0 + 3];
    atomicAdd(&g_cnt[c0], 1); atomicAdd(&g_cnt[c1], 1);
    atomicAdd(&g_cnt[c2], 1); atomicAdd(&g_cnt[c3], 1);

#pragma unroll 1
    for (int l = 0; l < NLAY; l++) {
        const float2* w1l = sw1 + l * 256;
        const float*  b1l = sb1 + l * 16;
        const float*  w2l = sw2 + l * 16;
        float bias2 = sb2[l];
        float s0 = bias2, s1 = bias2, s2 = bias2, s3 = bias2;
#pragma unroll
        for (int j = 0; j < FE; j++) {
            float bj = b1l[j];
            unsigned long long h01 = pk2(bj, bj);
            unsigned long long h23 = h01;
            const ulonglong2* wrow = (const ulonglong2*)(w1l + j * 16);
#pragma unroll
            for (int k = 0; k < FE; k += 2) {
                ulonglong2 w = wrow[k >> 1];
                h01 = fma2(a01[k], w.x, h01);
                h23 = fma2(a23[k], w.x, h23);
                h01 = fma2(a01[k + 1], w.y, h01);
                h23 = fma2(a23[k + 1], w.y, h23);
            }
            float h0, h1, h2, h3;
            upk2(h0, h1, h01); upk2(h2, h3, h23);
            float w2j = w2l[j];
            s0 = fmaf(fmaxf(h0, 0.f), w2j, s0);
            s1 = fmaf(fmaxf(h1, 0.f), w2j, s1);
            s2 = fmaf(fmaxf(h2, 0.f), w2j, s2);
            s3 = fmaf(fmaxf(h3, 0.f), w2j, s3);
        }
        float w0 = __fdividef(1.f, 1.f + __expf(-s0));
        float w1 = __fdividef(1.f, 1.f + __expf(-s1));
        float w2v = __fdividef(1.f, 1.f + __expf(-s2));
        float w3 = __fdividef(1.f, 1.f + __expf(-s3));
        *(float4*)&g_w[(size_t)l * EE + e0] = make_float4(w0, w1, w2v, w3);
        atomicAdd(&g_dis2[c0 * 8 + l], w0);
        atomicAdd(&g_dis2[c1 * 8 + l], w1);
        atomicAdd(&g_dis2[c2 * 8 + l], w2v);
        atomicAdd(&g_dis2[c3 * 8 + l], w3);
    }
}

// ---------------- CSR offsets ----------------
__global__ void k_scan() {
    __shared__ int sums[1024];
    const int CH = (NN + 1023) / 1024;
    int t = threadIdx.x;
    int base = t * CH;
    int s = 0;
    for (int i = 0; i < CH; i++) {
        int idx = base + i;
        if (idx < NN) s += g_cnt[idx];
    }
    sums[t] = s;
    __syncthreads();
    for (int off = 1; off < 1024; off <<= 1) {
        int v = 0;
        if (t >= off) v = sums[t - off];
        __syncthreads();
        sums[t] += v;
        __syncthreads();
    }
    int excl = (t == 0) ? 0 : sums[t - 1];
    for (int i = 0; i < CH; i++) {
        int idx = base + i;
        if (idx < NN) {
            int c = g_cnt[idx];
            g_off[idx] = excl;
            excl += c;
        }
    }
    if (t == 1023) g_off[NN] = excl;
}

__global__ void k_dis() {
    int i = blockIdx.x * blockDim.x + threadIdx.x;
    if (i < NN * 8) g_dis2[i] = rsqrtf(g_dis2[i] + 1.0f);
}

// ---------------- CSR fill + gcn_norm ----------------
__global__ void k_fillnorm(const int* __restrict__ row, const int* __restrict__ col) {
    int e = blockIdx.x * blockDim.x + threadIdx.x;
    if (e >= EE) return;
    int r = row[e], c = col[e];
    int p = g_off[c] + atomicAdd(&g_cnt2[c], 1);
    float4 dr0 = *(const float4*)&g_dis2[r * 8];
    float4 dr1 = *(const float4*)&g_dis2[r * 8 + 4];
    float4 dc0 = *(const float4*)&g_dis2[c * 8];
    float4 dc1 = *(const float4*)&g_dis2[c * 8 + 4];
    float dr[7] = {dr0.x, dr0.y, dr0.z, dr0.w, dr1.x, dr1.y, dr1.z};
    float dc[7] = {dc0.x, dc0.y, dc0.z, dc0.w, dc1.x, dc1.y, dc1.z};
#pragma unroll
    for (int l = 0; l < NLAY; l++) {
        float w = g_w[(size_t)l * EE + e];
        g_epk[(size_t)l * EE + p] = make_int2(r, __float_as_int(dr[l] * w * dc[l]));
    }
}

// ---------------- node GEMM: 128x64 tile, 128 threads, 8x8 register tile ----------------
// Conflict-free mapping (round-9): rows rg+16i, cols cg*4 + {0..3} / +32.
// Output stored as fp16 (gather operand).
#define SX_STRIDE  68
#define GEMM_SMEM  ((128 * SX_STRIDE + 64 * SX_STRIDE) * 4)

__global__ void __launch_bounds__(128) k_gemm(const float* __restrict__ x,
                                              const float* __restrict__ lw,
                                              __half* __restrict__ outh,
                                              const double* __restrict__ bns) {
    extern __shared__ __align__(16) float dsm[];
    float (*sx)[SX_STRIDE]  = (float(*)[SX_STRIDE])dsm;                      // [row][k]
    float (*swt)[SX_STRIDE] = (float(*)[SX_STRIDE])(dsm + 128 * SX_STRIDE);  // [k][c]
    __shared__ float smu[CC], sinv[CC];
    int t = threadIdx.x;
#pragma unroll
    for (int i = 0; i < 32; i++) {
        int e = i * 128 + t;
        int c = e >> 6, k = e & 63;
        swt[k][c] = lw[e];
    }
    if (bns != nullptr && t < CC) {
        double s = 0.0, q = 0.0;
#pragma unroll
        for (int cp = 0; cp < 8; cp++) {
            s += bns[cp * 128 + t];
            q += bns[cp * 128 + 64 + t];
        }
        double mu = s * (1.0 / NN);
        double var = q * (1.0 / NN) - mu * mu;
        smu[t] = (float)mu;
        sinv[t] = rsqrtf((float)var + EPSV);
    }
    __syncthreads();
    int row0 = blockIdx.x * 128;
#pragma unroll
    for (int i = 0; i < 16; i++) {
        int idx = i * 128 + t;
        int r = idx >> 4, kq = (idx & 15) * 4;
        int gr = row0 + r;
        float4 v = (gr < NN) ? *(const float4*)&x[gr * CC + kq]
                             : make_float4(0.f, 0.f, 0.f, 0.f);
        if (bns != nullptr) {
            v.x = fmaxf((v.x - smu[kq + 0]) * sinv[kq + 0], 0.f);
            v.y = fmaxf((v.y - smu[kq + 1]) * sinv[kq + 1], 0.f);
            v.z = fmaxf((v.z - smu[kq + 2]) * sinv[kq + 2], 0.f);
            v.w = fmaxf((v.w - smu[kq + 3]) * sinv[kq + 3], 0.f);
        }
        *(float4*)&sx[r][kq] = v;
    }
    __syncthreads();

    int rg = t >> 3;          // rows rg + 16*i, i = 0..7
    int cg = (t & 7) * 4;     // cols cg..cg+3 and cg+32..cg+35
    float acc[8][8];
#pragma unroll
    for (int i = 0; i < 8; i++)
#pragma unroll
        for (int j = 0; j < 8; j++) acc[i][j] = 0.f;

#pragma unroll 1
    for (int kb = 0; kb < CC; kb += 4) {
        float4 a[8];
#pragma unroll
        for (int i = 0; i < 8; i++) a[i] = *(const float4*)&sx[rg + 16 * i][kb];
        float4 b0[4], b1[4];
#pragma unroll
        for (int j = 0; j < 4; j++) {
            b0[j] = *(const float4*)&swt[kb + j][cg];
            b1[j] = *(const float4*)&swt[kb + j][cg + 32];
        }
#pragma unroll
        for (int i = 0; i < 8; i++) {
            float av[4] = {a[i].x, a[i].y, a[i].z, a[i].w};
#pragma unroll
            for (int j = 0; j < 4; j++) {
                acc[i][0] = fmaf(av[j], b0[j].x, acc[i][0]);
                acc[i][1] = fmaf(av[j], b0[j].y, acc[i][1]);
                acc[i][2] = fmaf(av[j], b0[j].z, acc[i][2]);
                acc[i][3] = fmaf(av[j], b0[j].w, acc[i][3]);
                acc[i][4] = fmaf(av[j], b1[j].x, acc[i][4]);
                acc[i][5] = fmaf(av[j], b1[j].y, acc[i][5]);
                acc[i][6] = fmaf(av[j], b1[j].z, acc[i][6]);
                acc[i][7] = fmaf(av[j], b1[j].w, acc[i][7]);
            }
        }
    }
#pragma unroll
    for (int i = 0; i < 8; i++) {
        int gr = row0 + rg + 16 * i;
        if (gr < NN) {
            uint2 s0, s1;
            *(__half2*)&s0.x = __floats2half2_rn(acc[i][0], acc[i][1]);
            *(__half2*)&s0.y = __floats2half2_rn(acc[i][2], acc[i][3]);
            *(__half2*)&s1.x = __floats2half2_rn(acc[i][4], acc[i][5]);
            *(__half2*)&s1.y = __floats2half2_rn(acc[i][6], acc[i][7]);
            *(uint2*)&outh[gr * CC + cg] = s0;
            *(uint2*)&outh[gr * CC + cg + 32] = s1;
        }
    }
}

// ---------------- message gather: warp/node, fp16 rows, smem staging, 8-deep ----------------
// mode 0: out = acc; mode 1: out = acc + skipA; mode 2: pool relu(acc+skipA+skipB)
__global__ void __launch_bounds__(512) k_gather(
    int l, const __half2* __restrict__ xh, float* __restrict__ out,
    const float* __restrict__ skipA, const float* __restrict__ skipB,
    const int* __restrict__ batch, int mode, int statslot)
{
    __shared__ __align__(16) int2 sed[16][32];
    __shared__ float ssum[16][64];
    __shared__ float ssq[16][64];
    int t = threadIdx.x;
    int w = t >> 5, lane = t & 31;
    int node = blockIdx.x * 16 + w;

    float d = g_dis2[node * 8 + l];
    float dd = d * d;
    float2 self = __half22float2(xh[node * 32 + lane]);
    float ax = self.x * dd, ay = self.y * dd;

    int s0 = g_off[node], e0 = g_off[node + 1];
    const int2* ep = g_epk + (size_t)l * EE;
    for (int j0 = s0; j0 < e0; j0 += 32) {
        int idx = j0 + lane;
        int2 p = (idx < e0) ? ep[idx] : make_int2(0, 0);
        sed[w][lane] = p;
        __syncwarp();
        int cnt = e0 - j0; if (cnt > 32) cnt = 32;
        int cntp = (cnt + 7) & ~7;
        for (int k = 0; k < cntp; k += 8) {
            int4 q0 = *(const int4*)&sed[w][k];
            int4 q1 = *(const int4*)&sed[w][k + 2];
            int4 q2 = *(const int4*)&sed[w][k + 4];
            int4 q3 = *(const int4*)&sed[w][k + 6];
            __half2 h0 = xh[(size_t)q0.x * 32 + lane];
            __half2 h1 = xh[(size_t)q0.z * 32 + lane];
            __half2 h2 = xh[(size_t)q1.x * 32 + lane];
            __half2 h3 = xh[(size_t)q1.z * 32 + lane];
            __half2 h4 = xh[(size_t)q2.x * 32 + lane];
            __half2 h5 = xh[(size_t)q2.z * 32 + lane];
            __half2 h6 = xh[(size_t)q3.x * 32 + lane];
            __half2 h7 = xh[(size_t)q3.z * 32 + lane];
            float n0 = __int_as_float(q0.y), n1 = __int_as_float(q0.w);
            float n2 = __int_as_float(q1.y), n3 = __int_as_float(q1.w);
            float n4 = __int_as_float(q2.y), n5 = __int_as_float(q2.w);
            float n6 = __int_as_float(q3.y), n7 = __int_as_float(q3.w);
            float2 v0 = __half22float2(h0);
            float2 v1 = __half22float2(h1);
            float2 v2 = __half22float2(h2);
            float2 v3 = __half22float2(h3);
            float2 v4 = __half22float2(h4);
            float2 v5 = __half22float2(h5);
            float2 v6 = __half22float2(h6);
            float2 v7 = __half22float2(h7);
            ax = fmaf(v0.x, n0, ax); ay = fmaf(v0.y, n0, ay);
            ax = fmaf(v1.x, n1, ax); ay = fmaf(v1.y, n1, ay);
            ax = fmaf(v2.x, n2, ax); ay = fmaf(v2.y, n2, ay);
            ax = fmaf(v3.x, n3, ax); ay = fmaf(v3.y, n3, ay);
            ax = fmaf(v4.x, n4, ax); ay = fmaf(v4.y, n4, ay);
            ax = fmaf(v5.x, n5, ax); ay = fmaf(v5.y, n5, ay);
            ax = fmaf(v6.x, n6, ax); ay = fmaf(v6.y, n6, ay);
            ax = fmaf(v7.x, n7, ax); ay = fmaf(v7.y, n7, ay);
        }
        __syncwarp();
    }

    int base = node * 64 + lane * 2;
    float vx = ax, vy = ay;
    if (mode == 1) { vx += skipA[base]; vy += skipA[base + 1]; }
    if (mode == 2) {
        vx = fmaxf(ax + skipA[base] + skipB[base], 0.f);
        vy = fmaxf(ay + skipA[base + 1] + skipB[base + 1], 0.f);
        int g = batch[node];
        atomicMax(&g_pool[g * CC + lane * 2], __float_as_uint(vx));
        atomicMax(&g_pool[g * CC + lane * 2 + 1], __float_as_uint(vy));
    } else {
        float2 o; o.x = vx; o.y = vy;
        ((float2*)out)[node * 32 + lane] = o;
    }

    if (statslot >= 0) {
        ssum[w][lane * 2] = vx; ssum[w][lane * 2 + 1] = vy;
        ssq[w][lane * 2] = vx * vx; ssq[w][lane * 2 + 1] = vy * vy;
        __syncthreads();
        if (t < 64) {
            float s = 0.f, q = 0.f;
#pragma unroll
            for (int ww = 0; ww < 16; ww++) { s += ssum[ww][t]; q += ssq[ww][t]; }
            double* slot = g_bn + statslot * 1024 + (blockIdx.x & 7) * 128;
            atomicAdd(&slot[t], (double)s);
            atomicAdd(&slot[64 + t], (double)q);
        }
    }
}

// ---------------- final linear ----------------
__global__ void k_fin(const float* __restrict__ lw, const float* __restrict__ lb,
                      float* __restrict__ out) {
    __shared__ float sw[NCLSV * CC];
    __shared__ float sb[NCLSV];
    int t = threadIdx.x;
    for (int i = t; i < NCLSV * CC; i += blockDim.x) sw[i] = lw[i];
    if (t < NCLSV) sb[t] = lb[t];
    __syncthreads();
    int g = blockIdx.x * blockDim.x + t;
    if (g >= GG) return;
    float acc[NCLSV];
#pragma unroll
    for (int j = 0; j < NCLSV; j++) acc[j] = sb[j];
    for (int k = 0; k < CC; k++) {
        float p = __uint_as_float(g_pool[g * CC + k]);
#pragma unroll
        for (int j = 0; j < NCLSV; j++) acc[j] += p * sw[j * CC + k];
    }
#pragma unroll
    for (int j = 0; j < NCLSV; j++) out[g * NCLSV + j] = acc[j];
}

// ---------------- host launcher ----------------
extern "C" void kernel_launch(void* const* d_in, const int* in_sizes, int n_in,
                              void* d_out, int out_size) {
    const float* x      = (const float*)d_in[0];
    const int*   ei     = (const int*)d_in[1];
    const int*   batch  = (const int*)d_in[2];
    const float* ea     = (const float*)d_in[4];
    const float* c1_lw  = (const float*)d_in[5];
    const float* c1_w1  = (const float*)d_in[6];
    const float* c1_b1  = (const float*)d_in[7];
    const float* c1_w2  = (const float*)d_in[8];
    const float* c1_b2  = (const float*)d_in[9];
    const float* h1_lw  = (const float*)d_in[10];
    const float* h1_w1  = (const float*)d_in[11];
    const float* h1_b1  = (const float*)d_in[12];
    const float* h1_w2  = (const float*)d_in[13];
    const float* h1_b2  = (const float*)d_in[14];
    const float* h2_lw  = (const float*)d_in[15];
    const float* h2_w1  = (const float*)d_in[16];
    const float* h2_b1  = (const float*)d_in[17];
    const float* h2_w2  = (const float*)d_in[18];
    const float* h2_b2  = (const float*)d_in[19];
    const float* lin_w  = (const float*)d_in[20];
    const float* lin_b  = (const float*)d_in[21];

    const int* row = ei;
    const int* col = ei + EE;

    float *A, *B, *C, *D;
    __half* XLH;
    double* BN;
    cudaGetSymbolAddress((void**)&A,   g_bufA);
    cudaGetSymbolAddress((void**)&B,   g_bufB);
    cudaGetSymbolAddress((void**)&C,   g_bufC);
    cudaGetSymbolAddress((void**)&D,   g_bufD);
    cudaGetSymbolAddress((void**)&XLH, g_xlh);
    cudaGetSymbolAddress((void**)&BN,  g_bn);

    cudaFuncSetAttribute(k_gemm, cudaFuncAttributeMaxDynamicSharedMemorySize, GEMM_SMEM);

    const int EB  = (EE + 255) / 256;             // 3125
    const int EB4 = (EE / 4 + 255) / 256;         // 782
    const int ZB  = (NN * 8 + 255) / 256;         // 1563

    MlpAll mp;
    mp.p[0] = {c1_w1, c1_b1, c1_w2, c1_b2};
    for (int i = 0; i < 3; i++) {
        mp.p[1 + i] = {h1_w1 + i * FE * FE, h1_b1 + i * FE, h1_w2 + i * FE, h1_b2 + i};
        mp.p[4 + i] = {h2_w1 + i * FE * FE, h2_b1 + i * FE, h2_w2 + i * FE, h2_b2 + i};
    }

    const int GEMM_B = (NN + 127) / 128;  // 391
    const int GATH_B = NN / 16;           // 3125

    k_zero<<<ZB, 256>>>();                                        // 0
    k_mlp<<<EB4, 256>>>(ea, col, mp);                             // 1
    k_scan<<<1, 1024>>>();                                        // 2
    k_gemm<<<GEMM_B, 128, GEMM_SMEM>>>(x, c1_lw, XLH, nullptr);   // 3  <- profiled slot
    k_dis<<<ZB, 256>>>();                                         // 4
    k_fillnorm<<<EB, 256>>>(row, col);                            // 5

    k_gather<<<GATH_B, 512>>>(0, (const __half2*)XLH, A, nullptr, nullptr, nullptr, 0, 0);
    k_gemm<<<GEMM_B, 128, GEMM_SMEM>>>(A, h1_lw + 0 * CC * CC, XLH, BN + 0 * 1024);
    k_gather<<<GATH_B, 512>>>(1, (const __half2*)XLH, B, nullptr, nullptr, nullptr, 0, 1);
    k_gemm<<<GEMM_B, 128, GEMM_SMEM>>>(B, h1_lw + 1 * CC * CC, XLH, BN + 1 * 1024);
    k_gather<<<GATH_B, 512>>>(2, (const __half2*)XLH, C, nullptr, nullptr, nullptr, 0, 2);
    k_gemm<<<GEMM_B, 128, GEMM_SMEM>>>(C, h1_lw + 2 * CC * CC, XLH, BN + 2 * 1024);
    k_gather<<<GATH_B, 512>>>(3, (const __half2*)XLH, D, A, nullptr, nullptr, 1, 3);   // D = x1
    k_gemm<<<GEMM_B, 128, GEMM_SMEM>>>(D, h2_lw + 0 * CC * CC, XLH, BN + 3 * 1024);
    k_gather<<<GATH_B, 512>>>(4, (const __half2*)XLH, B, nullptr, nullptr, nullptr, 0, 4);
    k_gemm<<<GEMM_B, 128, GEMM_SMEM>>>(B, h2_lw + 1 * CC * CC, XLH, BN + 4 * 1024);
    k_gather<<<GATH_B, 512>>>(5, (const __half2*)XLH, C, nullptr, nullptr, nullptr, 0, 5);
    k_gemm<<<GEMM_B, 128, GEMM_SMEM>>>(C, h2_lw + 2 * CC * CC, XLH, BN + 5 * 1024);
    k_gather<<<GATH_B, 512>>>(6, (const __half2*)XLH, nullptr, A, D, batch, 2, -1);    // pool
    k_fin<<<2, 256>>>(lin_w, lin_b, (float*)d_out);
}

// round 12
// speedup vs baseline: 1.1489x; 1.0196x over previous
#include <cuda_runtime.h>
#include <cuda_fp16.h>
#include <math.h>

#define NN    50000
#define EE    800000
#define CC    64
#define FE    16
#define NLAY  7
#define GG    512
#define NCLSV 10
#define EPSV  1e-5f

// ---------------- f32x2 packed helpers (used in MLP only) ----------------
__device__ __forceinline__ unsigned long long pk2(float lo, float hi) {
    unsigned long long r;
    asm("mov.b64 %0, {%1, %2};" : "=l"(r) : "f"(lo), "f"(hi));
    return r;
}
__device__ __forceinline__ void upk2(float& lo, float& hi, unsigned long long v) {
    asm("mov.b64 {%0, %1}, %2;" : "=f"(lo), "=f"(hi) : "l"(v));
}
__device__ __forceinline__ unsigned long long fma2(unsigned long long a,
                                                   unsigned long long b,
                                                   unsigned long long c) {
    unsigned long long d;
    asm("fma.rn.f32x2 %0, %1, %2, %3;" : "=l"(d) : "l"(a), "l"(b), "l"(c));
    return d;
}

// ---------------- static device scratch ----------------
__device__ float  g_w[NLAY * EE];
__device__ float  g_dis2[NN * 8];
__device__ int2   g_epk[NLAY * EE];
__device__ int    g_off[NN + 1];
__device__ int    g_cnt[NN];
__device__ int    g_cnt2[NN];
__device__ float  g_bufA[NN * CC];
__device__ float  g_bufB[NN * CC];
__device__ float  g_bufC[NN * CC];
__device__ float  g_bufD[NN * CC];
__device__ __half g_xlh[NN * CC];         // fp16 gather operand
__device__ double g_bn[6 * 8 * 2 * CC];   // 6 slots x 8 spread copies x (sum64, sq64)
__device__ unsigned g_pool[GG * CC];

// ---------------- zero ----------------
__global__ void k_zero() {
    int i = blockIdx.x * blockDim.x + threadIdx.x;
    if (i < NN) { g_cnt[i] = 0; g_cnt2[i] = 0; }
    if (i < NN * 8) g_dis2[i] = 0.f;
    if (i < GG * CC) g_pool[i] = 0u;
    if (i < 6 * 8 * 2 * CC) g_bn[i] = 0.0;
}

// ---------------- edge MLPs: 4 edges/thread, f32x2, LDS.128 weight loads ----------------
struct MlpP { const float* w1; const float* b1; const float* w2; const float* b2; };
struct MlpAll { MlpP p[NLAY]; };

__global__ void __launch_bounds__(256) k_mlp(const float* __restrict__ ea,
                                             const int* __restrict__ col, MlpAll mp) {
    __shared__ __align__(16) float2 sw1[NLAY * FE * FE];
    __shared__ float  sb1[NLAY * FE];
    __shared__ float  sw2[NLAY * FE];
    __shared__ float  sb2[NLAY];
    int t = threadIdx.x;
    for (int i = t; i < NLAY * FE * FE; i += 256) {
        int l = i >> 8;
        float v = mp.p[l].w1[i & 255];
        sw1[i] = make_float2(v, v);
    }
    for (int i = t; i < NLAY * FE; i += 256) {
        int l = i >> 4;
        sb1[i] = mp.p[l].b1[i & 15];
        sw2[i] = mp.p[l].w2[i & 15];
    }
    if (t < NLAY) sb2[t] = mp.p[t].b2[0];
    __syncthreads();

    int e0 = (blockIdx.x * 256 + t) * 4;
    if (e0 >= EE) return;

    unsigned long long a01[FE], a23[FE];
    {
        float a[4][FE];
#pragma unroll
        for (int i = 0; i < 4; i++) {
            const float4* p4 = (const float4*)(ea + (size_t)(e0 + i) * FE);
#pragma unroll
            for (int q = 0; q < 4; q++) {
                float4 v = p4[q];
                a[i][4 * q] = v.x; a[i][4 * q + 1] = v.y;
                a[i][4 * q + 2] = v.z; a[i][4 * q + 3] = v.w;
            }
        }
#pragma unroll
        for (int k = 0; k < FE; k++) {
            a01[k] = pk2(a[0][k], a[1][k]);
            a23[k] = pk2(a[2][k], a[3][k]);
        }
    }
    int c0 = col[e0], c1 = col[e0 + 1], c2 = col[e0 + 2], c3 = col[e0 + 3];
    atomicAdd(&g_cnt[c0], 1); atomicAdd(&g_cnt[c1], 1);
    atomicAdd(&g_cnt[c2], 1); atomicAdd(&g_cnt[c3], 1);

#pragma unroll 1
    for (int l = 0; l < NLAY; l++) {
        const float2* w1l = sw1 + l * 256;
        const float*  b1l = sb1 + l * 16;
        const float*  w2l = sw2 + l * 16;
        float bias2 = sb2[l];
        float s0 = bias2, s1 = bias2, s2 = bias2, s3 = bias2;
#pragma unroll
        for (int j = 0; j < FE; j++) {
            float bj = b1l[j];
            unsigned long long h01 = pk2(bj, bj);
            unsigned long long h23 = h01;
            const ulonglong2* wrow = (const ulonglong2*)(w1l + j * 16);
#pragma unroll
            for (int k = 0; k < FE; k += 2) {
                ulonglong2 w = wrow[k >> 1];
                h01 = fma2(a01[k], w.x, h01);
                h23 = fma2(a23[k], w.x, h23);
                h01 = fma2(a01[k + 1], w.y, h01);
                h23 = fma2(a23[k + 1], w.y, h23);
            }
            float h0, h1, h2, h3;
            upk2(h0, h1, h01); upk2(h2, h3, h23);
            float w2j = w2l[j];
            s0 = fmaf(fmaxf(h0, 0.f), w2j, s0);
            s1 = fmaf(fmaxf(h1, 0.f), w2j, s1);
            s2 = fmaf(fmaxf(h2, 0.f), w2j, s2);
            s3 = fmaf(fmaxf(h3, 0.f), w2j, s3);
        }
        float w0 = __fdividef(1.f, 1.f + __expf(-s0));
        float w1 = __fdividef(1.f, 1.f + __expf(-s1));
        float w2v = __fdividef(1.f, 1.f + __expf(-s2));
        float w3 = __fdividef(1.f, 1.f + __expf(-s3));
        *(float4*)&g_w[(size_t)l * EE + e0] = make_float4(w0, w1, w2v, w3);
        atomicAdd(&g_dis2[c0 * 8 + l], w0);
        atomicAdd(&g_dis2[c1 * 8 + l], w1);
        atomicAdd(&g_dis2[c2 * 8 + l], w2v);
        atomicAdd(&g_dis2[c3 * 8 + l], w3);
    }
}

// ---------------- CSR offsets ----------------
__global__ void k_scan() {
    __shared__ int sums[1024];
    const int CH = (NN + 1023) / 1024;
    int t = threadIdx.x;
    int base = t * CH;
    int s = 0;
    for (int i = 0; i < CH; i++) {
        int idx = base + i;
        if (idx < NN) s += g_cnt[idx];
    }
    sums[t] = s;
    __syncthreads();
    for (int off = 1; off < 1024; off <<= 1) {
        int v = 0;
        if (t >= off) v = sums[t - off];
        __syncthreads();
        sums[t] += v;
        __syncthreads();
    }
    int excl = (t == 0) ? 0 : sums[t - 1];
    for (int i = 0; i < CH; i++) {
        int idx = base + i;
        if (idx < NN) {
            int c = g_cnt[idx];
            g_off[idx] = excl;
            excl += c;
        }
    }
    if (t == 1023) g_off[NN] = excl;
}

__global__ void k_dis() {
    int i = blockIdx.x * blockDim.x + threadIdx.x;
    if (i < NN * 8) g_dis2[i] = rsqrtf(g_dis2[i] + 1.0f);
}

// ---------------- CSR fill + gcn_norm ----------------
__global__ void k_fillnorm(const int* __restrict__ row, const int* __restrict__ col) {
    int e = blockIdx.x * blockDim.x + threadIdx.x;
    if (e >= EE) return;
    int r = row[e], c = col[e];
    int p = g_off[c] + atomicAdd(&g_cnt2[c], 1);
    float4 dr0 = *(const float4*)&g_dis2[r * 8];
    float4 dr1 = *(const float4*)&g_dis2[r * 8 + 4];
    float4 dc0 = *(const float4*)&g_dis2[c * 8];
    float4 dc1 = *(const float4*)&g_dis2[c * 8 + 4];
    float dr[7] = {dr0.x, dr0.y, dr0.z, dr0.w, dr1.x, dr1.y, dr1.z};
    float dc[7] = {dc0.x, dc0.y, dc0.z, dc0.w, dc1.x, dc1.y, dc1.z};
#pragma unroll
    for (int l = 0; l < NLAY; l++) {
        float w = g_w[(size_t)l * EE + e];
        g_epk[(size_t)l * EE + p] = make_int2(r, __float_as_int(dr[l] * w * dc[l]));
    }
}

// ---------------- node GEMM: 64x64 tile, 128 threads, 4x8 register tile ----------------
// Conflict-free: rows rg+16i (i=0..3), cols cg*4 + {0..3} and cg*4 + 32 + {0..3}.
// smem 34.8KB -> 6 blocks/SM, all 782 blocks resident in one wave.
#define SX_STRIDE  68
#define GEMM_SMEM  ((64 * SX_STRIDE + 64 * SX_STRIDE) * 4)

__global__ void __launch_bounds__(128) k_gemm(const float* __restrict__ x,
                                              const float* __restrict__ lw,
                                              __half* __restrict__ outh,
                                              const double* __restrict__ bns) {
    extern __shared__ __align__(16) float dsm[];
    float (*sx)[SX_STRIDE]  = (float(*)[SX_STRIDE])dsm;                     // [row][k]
    float (*swt)[SX_STRIDE] = (float(*)[SX_STRIDE])(dsm + 64 * SX_STRIDE);  // [k][c]
    __shared__ float smu[CC], sinv[CC];
    int t = threadIdx.x;
    // coalesced weight read, transpose into smem: swt[k][c] = lw[c][k]
#pragma unroll
    for (int i = 0; i < 32; i++) {
        int e = i * 128 + t;
        int c = e >> 6, k = e & 63;
        swt[k][c] = lw[e];
    }
    if (bns != nullptr && t < CC) {
        double s = 0.0, q = 0.0;
#pragma unroll
        for (int cp = 0; cp < 8; cp++) {
            s += bns[cp * 128 + t];
            q += bns[cp * 128 + 64 + t];
        }
        double mu = s * (1.0 / NN);
        double var = q * (1.0 / NN) - mu * mu;
        smu[t] = (float)mu;
        sinv[t] = rsqrtf((float)var + EPSV);
    }
    __syncthreads();
    int row0 = blockIdx.x * 64;
#pragma unroll
    for (int i = 0; i < 8; i++) {
        int idx = i * 128 + t;
        int r = idx >> 4, kq = (idx & 15) * 4;
        int gr = row0 + r;
        float4 v = (gr < NN) ? *(const float4*)&x[gr * CC + kq]
                             : make_float4(0.f, 0.f, 0.f, 0.f);
        if (bns != nullptr) {
            v.x = fmaxf((v.x - smu[kq + 0]) * sinv[kq + 0], 0.f);
            v.y = fmaxf((v.y - smu[kq + 1]) * sinv[kq + 1], 0.f);
            v.z = fmaxf((v.z - smu[kq + 2]) * sinv[kq + 2], 0.f);
            v.w = fmaxf((v.w - smu[kq + 3]) * sinv[kq + 3], 0.f);
        }
        *(float4*)&sx[r][kq] = v;
    }
    __syncthreads();

    int rg = t >> 3;          // rows rg + 16*i, i = 0..3
    int cg = (t & 7) * 4;     // cols cg..cg+3 and cg+32..cg+35
    float acc[4][8];
#pragma unroll
    for (int i = 0; i < 4; i++)
#pragma unroll
        for (int j = 0; j < 8; j++) acc[i][j] = 0.f;

#pragma unroll 1
    for (int kb = 0; kb < CC; kb += 4) {
        float4 a[4];
#pragma unroll
        for (int i = 0; i < 4; i++) a[i] = *(const float4*)&sx[rg + 16 * i][kb];
        float4 b0[4], b1[4];
#pragma unroll
        for (int j = 0; j < 4; j++) {
            b0[j] = *(const float4*)&swt[kb + j][cg];
            b1[j] = *(const float4*)&swt[kb + j][cg + 32];
        }
#pragma unroll
        for (int i = 0; i < 4; i++) {
            float av[4] = {a[i].x, a[i].y, a[i].z, a[i].w};
#pragma unroll
            for (int j = 0; j < 4; j++) {
                acc[i][0] = fmaf(av[j], b0[j].x, acc[i][0]);
                acc[i][1] = fmaf(av[j], b0[j].y, acc[i][1]);
                acc[i][2] = fmaf(av[j], b0[j].z, acc[i][2]);
                acc[i][3] = fmaf(av[j], b0[j].w, acc[i][3]);
                acc[i][4] = fmaf(av[j], b1[j].x, acc[i][4]);
                acc[i][5] = fmaf(av[j], b1[j].y, acc[i][5]);
                acc[i][6] = fmaf(av[j], b1[j].z, acc[i][6]);
                acc[i][7] = fmaf(av[j], b1[j].w, acc[i][7]);
            }
        }
    }
#pragma unroll
    for (int i = 0; i < 4; i++) {
        int gr = row0 + rg + 16 * i;
        if (gr < NN) {
            uint2 s0, s1;
            *(__half2*)&s0.x = __floats2half2_rn(acc[i][0], acc[i][1]);
            *(__half2*)&s0.y = __floats2half2_rn(acc[i][2], acc[i][3]);
            *(__half2*)&s1.x = __floats2half2_rn(acc[i][4], acc[i][5]);
            *(__half2*)&s1.y = __floats2half2_rn(acc[i][6], acc[i][7]);
            *(uint2*)&outh[gr * CC + cg] = s0;
            *(uint2*)&outh[gr * CC + cg + 32] = s1;
        }
    }
}

// ---------------- message gather: warp/node, 256-thr blocks, fp16 rows ----------------
// mode 0: out = acc; mode 1: out = acc + skipA; mode 2: pool relu(acc+skipA+skipB)
__global__ void __launch_bounds__(256) k_gather(
    int l, const __half2* __restrict__ xh, float* __restrict__ out,
    const float* __restrict__ skipA, const float* __restrict__ skipB,
    const int* __restrict__ batch, int mode, int statslot)
{
    __shared__ __align__(16) int2 sed[8][32];
    __shared__ float ssum[8][64];
    __shared__ float ssq[8][64];
    int t = threadIdx.x;
    int w = t >> 5, lane = t & 31;
    int node = blockIdx.x * 8 + w;

    // issue first edge-chunk load ASAP, overlap with dis/self loads
    int s0 = g_off[node], e0 = g_off[node + 1];
    const int2* ep = g_epk + (size_t)l * EE;
    int idx0 = s0 + lane;
    int2 p0 = (idx0 < e0) ? ep[idx0] : make_int2(0, 0);

    float d = g_dis2[node * 8 + l];
    float dd = d * d;
    float2 self = __half22float2(xh[node * 32 + lane]);
    float ax = self.x * dd, ay = self.y * dd;

    for (int j0 = s0; j0 < e0; j0 += 32) {
        int2 p = p0;
        sed[w][lane] = p;
        __syncwarp();
        // prefetch next chunk
        int idxn = j0 + 32 + lane;
        p0 = (idxn < e0) ? ep[idxn] : make_int2(0, 0);
        int cnt = e0 - j0; if (cnt > 32) cnt = 32;
        int cntp = (cnt + 7) & ~7;
        for (int k = 0; k < cntp; k += 8) {
            int4 q0 = *(const int4*)&sed[w][k];
            int4 q1 = *(const int4*)&sed[w][k + 2];
            int4 q2 = *(const int4*)&sed[w][k + 4];
            int4 q3 = *(const int4*)&sed[w][k + 6];
            __half2 h0 = xh[(size_t)q0.x * 32 + lane];
            __half2 h1 = xh[(size_t)q0.z * 32 + lane];
            __half2 h2 = xh[(size_t)q1.x * 32 + lane];
            __half2 h3 = xh[(size_t)q1.z * 32 + lane];
            __half2 h4 = xh[(size_t)q2.x * 32 + lane];
            __half2 h5 = xh[(size_t)q2.z * 32 + lane];
            __half2 h6 = xh[(size_t)q3.x * 32 + lane];
            __half2 h7 = xh[(size_t)q3.z * 32 + lane];
            float n0 = __int_as_float(q0.y), n1 = __int_as_float(q0.w);
            float n2 = __int_as_float(q1.y), n3 = __int_as_float(q1.w);
            float n4 = __int_as_float(q2.y), n5 = __int_as_float(q2.w);
            float n6 = __int_as_float(q3.y), n7 = __int_as_float(q3.w);
            float2 v0 = __half22float2(h0);
            float2 v1 = __half22float2(h1);
            float2 v2 = __half22float2(h2);
            float2 v3 = __half22float2(h3);
            float2 v4 = __half22float2(h4);
            float2 v5 = __half22float2(h5);
            float2 v6 = __half22float2(h6);
            float2 v7 = __half22float2(h7);
            ax = fmaf(v0.x, n0, ax); ay = fmaf(v0.y, n0, ay);
            ax = fmaf(v1.x, n1, ax); ay = fmaf(v1.y, n1, ay);
            ax = fmaf(v2.x, n2, ax); ay = fmaf(v2.y, n2, ay);
            ax = fmaf(v3.x, n3, ax); ay = fmaf(v3.y, n3, ay);
            ax = fmaf(v4.x, n4, ax); ay = fmaf(v4.y, n4, ay);
            ax = fmaf(v5.x, n5, ax); ay = fmaf(v5.y, n5, ay);
            ax = fmaf(v6.x, n6, ax); ay = fmaf(v6.y, n6, ay);
            ax = fmaf(v7.x, n7, ax); ay = fmaf(v7.y, n7, ay);
        }
        __syncwarp();
    }

    int base = node * 64 + lane * 2;
    float vx = ax, vy = ay;
    if (mode == 1) { vx += skipA[base]; vy += skipA[base + 1]; }
    if (mode == 2) {
        vx = fmaxf(ax + skipA[base] + skipB[base], 0.f);
        vy = fmaxf(ay + skipA[base + 1] + skipB[base + 1], 0.f);
        int g = batch[node];
        atomicMax(&g_pool[g * CC + lane * 2], __float_as_uint(vx));
        atomicMax(&g_pool[g * CC + lane * 2 + 1], __float_as_uint(vy));
    } else {
        float2 o; o.x = vx; o.y = vy;
        ((float2*)out)[node * 32 + lane] = o;
    }

    if (statslot >= 0) {
        ssum[w][lane * 2] = vx; ssum[w][lane * 2 + 1] = vy;
        ssq[w][lane * 2] = vx * vx; ssq[w][lane * 2 + 1] = vy * vy;
        __syncthreads();
        if (t < 64) {
            float s = 0.f, q = 0.f;
#pragma unroll
            for (int ww = 0; ww < 8; ww++) { s += ssum[ww][t]; q += ssq[ww][t]; }
            double* slot = g_bn + statslot * 1024 + (blockIdx.x & 7) * 128;
            atomicAdd(&slot[t], (double)s);
            atomicAdd(&slot[64 + t], (double)q);
        }
    }
}

// ---------------- final linear ----------------
__global__ void k_fin(const float* __restrict__ lw, const float* __restrict__ lb,
                      float* __restrict__ out) {
    __shared__ float sw[NCLSV * CC];
    __shared__ float sb[NCLSV];
    int t = threadIdx.x;
    for (int i = t; i < NCLSV * CC; i += blockDim.x) sw[i] = lw[i];
    if (t < NCLSV) sb[t] = lb[t];
    __syncthreads();
    int g = blockIdx.x * blockDim.x + t;
    if (g >= GG) return;
    float acc[NCLSV];
#pragma unroll
    for (int j = 0; j < NCLSV; j++) acc[j] = sb[j];
    for (int k = 0; k < CC; k++) {
        float p = __uint_as_float(g_pool[g * CC + k]);
#pragma unroll
        for (int j = 0; j < NCLSV; j++) acc[j] += p * sw[j * CC + k];
    }
#pragma unroll
    for (int j = 0; j < NCLSV; j++) out[g * NCLSV + j] = acc[j];
}

// ---------------- host launcher ----------------
extern "C" void kernel_launch(void* const* d_in, const int* in_sizes, int n_in,
                              void* d_out, int out_size) {
    const float* x      = (const float*)d_in[0];
    const int*   ei     = (const int*)d_in[1];
    const int*   batch  = (const int*)d_in[2];
    const float* ea     = (const float*)d_in[4];
    const float* c1_lw  = (const float*)d_in[5];
    const float* c1_w1  = (const float*)d_in[6];
    const float* c1_b1  = (const float*)d_in[7];
    const float* c1_w2  = (const float*)d_in[8];
    const float* c1_b2  = (const float*)d_in[9];
    const float* h1_lw  = (const float*)d_in[10];
    const float* h1_w1  = (const float*)d_in[11];
    const float* h1_b1  = (const float*)d_in[12];
    const float* h1_w2  = (const float*)d_in[13];
    const float* h1_b2  = (const float*)d_in[14];
    const float* h2_lw  = (const float*)d_in[15];
    const float* h2_w1  = (const float*)d_in[16];
    const float* h2_b1  = (const float*)d_in[17];
    const float* h2_w2  = (const float*)d_in[18];
    const float* h2_b2  = (const float*)d_in[19];
    const float* lin_w  = (const float*)d_in[20];
    const float* lin_b  = (const float*)d_in[21];

    const int* row = ei;
    const int* col = ei + EE;

    float *A, *B, *C, *D;
    __half* XLH;
    double* BN;
    cudaGetSymbolAddress((void**)&A,   g_bufA);
    cudaGetSymbolAddress((void**)&B,   g_bufB);
    cudaGetSymbolAddress((void**)&C,   g_bufC);
    cudaGetSymbolAddress((void**)&D,   g_bufD);
    cudaGetSymbolAddress((void**)&XLH, g_xlh);
    cudaGetSymbolAddress((void**)&BN,  g_bn);

    cudaFuncSetAttribute(k_gemm, cudaFuncAttributeMaxDynamicSharedMemorySize, GEMM_SMEM);

    const int EB  = (EE + 255) / 256;             // 3125
    const int EB4 = (EE / 4 + 255) / 256;         // 782
    const int ZB  = (NN * 8 + 255) / 256;         // 1563

    MlpAll mp;
    mp.p[0] = {c1_w1, c1_b1, c1_w2, c1_b2};
    for (int i = 0; i < 3; i++) {
        mp.p[1 + i] = {h1_w1 + i * FE * FE, h1_b1 + i * FE, h1_w2 + i * FE, h1_b2 + i};
        mp.p[4 + i] = {h2_w1 + i * FE * FE, h2_b1 + i * FE, h2_w2 + i * FE, h2_b2 + i};
    }

    const int GEMM_B = (NN + 63) / 64;    // 782
    const int GATH_B = NN / 8;            // 6250

    k_zero<<<ZB, 256>>>();                                        // 0
    k_mlp<<<EB4, 256>>>(ea, col, mp);                             // 1
    k_scan<<<1, 1024>>>();                                        // 2
    k_gemm<<<GEMM_B, 128, GEMM_SMEM>>>(x, c1_lw, XLH, nullptr);   // 3  <- profiled slot
    k_dis<<<ZB, 256>>>();                                         // 4
    k_fillnorm<<<EB, 256>>>(row, col);                            // 5

    k_gather<<<GATH_B, 256>>>(0, (const __half2*)XLH, A, nullptr, nullptr, nullptr, 0, 0);
    k_gemm<<<GEMM_B, 128, GEMM_SMEM>>>(A, h1_lw + 0 * CC * CC, XLH, BN + 0 * 1024);
    k_gather<<<GATH_B, 256>>>(1, (const __half2*)XLH, B, nullptr, nullptr, nullptr, 0, 1);
    k_gemm<<<GEMM_B, 128, GEMM_SMEM>>>(B, h1_lw + 1 * CC * CC, XLH, BN + 1 * 1024);
    k_gather<<<GATH_B, 256>>>(2, (const __half2*)XLH, C, nullptr, nullptr, nullptr, 0, 2);
    k_gemm<<<GEMM_B, 128, GEMM_SMEM>>>(C, h1_lw + 2 * CC * CC, XLH, BN + 2 * 1024);
    k_gather<<<GATH_B, 256>>>(3, (const __half2*)XLH, D, A, nullptr, nullptr, 1, 3);   // D = x1
    k_gemm<<<GEMM_B, 128, GEMM_SMEM>>>(D, h2_lw + 0 * CC * CC, XLH, BN + 3 * 1024);
    k_gather<<<GATH_B, 256>>>(4, (const __half2*)XLH, B, nullptr, nullptr, nullptr, 0, 4);
    k_gemm<<<GEMM_B, 128, GEMM_SMEM>>>(B, h2_lw + 1 * CC * CC, XLH, BN + 4 * 1024);
    k_gather<<<GATH_B, 256>>>(5, (const __half2*)XLH, C, nullptr, nullptr, nullptr, 0, 5);
    k_gemm<<<GEMM_B, 128, GEMM_SMEM>>>(C, h2_lw + 2 * CC * CC, XLH, BN + 5 * 1024);
    k_gather<<<GATH_B, 256>>>(6, (const __half2*)XLH, nullptr, A, D, batch, 2, -1);    // pool
    k_fin<<<2, 256>>>(lin_w, lin_b, (float*)d_out);
}

// round 13
// speedup vs baseline: 1.2161x; 1.0585x over previous
#include <cuda_runtime.h>
#include <cuda_fp16.h>
#include <math.h>

#define NN    50000
#define EE    800000
#define CC    64
#define FE    16
#define NLAY  7
#define GG    512
#define NCLSV 10
#define EPSV  1e-5f

// ---------------- f32x2 packed helpers (used in MLP only) ----------------
__device__ __forceinline__ unsigned long long pk2(float lo, float hi) {
    unsigned long long r;
    asm("mov.b64 %0, {%1, %2};" : "=l"(r) : "f"(lo), "f"(hi));
    return r;
}
__device__ __forceinline__ void upk2(float& lo, float& hi, unsigned long long v) {
    asm("mov.b64 {%0, %1}, %2;" : "=f"(lo), "=f"(hi) : "l"(v));
}
__device__ __forceinline__ unsigned long long fma2(unsigned long long a,
                                                   unsigned long long b,
                                                   unsigned long long c) {
    unsigned long long d;
    asm("fma.rn.f32x2 %0, %1, %2, %3;" : "=l"(d) : "l"(a), "l"(b), "l"(c));
    return d;
}

// ---------------- static device scratch ----------------
__device__ float  g_w8[(size_t)EE * 8];    // per-edge weights, edge order [e][8]
__device__ float  g_wcsr[(size_t)EE * 8];  // per-edge weights, CSR order [p][8]
__device__ int    g_srcw[EE];              // CSR slot -> src node
__device__ float  g_dis2[NN * 8];          // [node][8] rsqrt(deg+1)
__device__ int2   g_epk[(size_t)NLAY * EE];// CSR slot -> (src, norm_bits) per layer
__device__ int    g_off[NN + 1];
__device__ int    g_cnt[NN];
__device__ int    g_cnt2[NN];
__device__ float  g_bufA[NN * CC];
__device__ float  g_bufB[NN * CC];
__device__ float  g_bufC[NN * CC];
__device__ float  g_bufD[NN * CC];
__device__ __half g_xlh[NN * CC];          // fp16 gather operand
__device__ double g_bn[6 * 8 * 2 * CC];
__device__ unsigned g_pool[GG * CC];

// ---------------- zero ----------------
__global__ void k_zero() {
    int i = blockIdx.x * blockDim.x + threadIdx.x;
    if (i < NN) { g_cnt[i] = 0; g_cnt2[i] = 0; }
    if (i < GG * CC) g_pool[i] = 0u;
    if (i < 6 * 8 * 2 * CC) g_bn[i] = 0.0;
}

// ---------------- edge MLPs: 4 edges/thread, f32x2, no deg atomics ----------------
struct MlpP { const float* w1; const float* b1; const float* w2; const float* b2; };
struct MlpAll { MlpP p[NLAY]; };

__global__ void __launch_bounds__(256) k_mlp(const float* __restrict__ ea,
                                             const int* __restrict__ col, MlpAll mp) {
    __shared__ __align__(16) float2 sw1[NLAY * FE * FE];
    __shared__ float  sb1[NLAY * FE];
    __shared__ float  sw2[NLAY * FE];
    __shared__ float  sb2[NLAY];
    int t = threadIdx.x;
    for (int i = t; i < NLAY * FE * FE; i += 256) {
        int l = i >> 8;
        float v = mp.p[l].w1[i & 255];
        sw1[i] = make_float2(v, v);
    }
    for (int i = t; i < NLAY * FE; i += 256) {
        int l = i >> 4;
        sb1[i] = mp.p[l].b1[i & 15];
        sw2[i] = mp.p[l].w2[i & 15];
    }
    if (t < NLAY) sb2[t] = mp.p[t].b2[0];
    __syncthreads();

    int e0 = (blockIdx.x * 256 + t) * 4;
    if (e0 >= EE) return;

    unsigned long long a01[FE], a23[FE];
    {
        float a[4][FE];
#pragma unroll
        for (int i = 0; i < 4; i++) {
            const float4* p4 = (const float4*)(ea + (size_t)(e0 + i) * FE);
#pragma unroll
            for (int q = 0; q < 4; q++) {
                float4 v = p4[q];
                a[i][4 * q] = v.x; a[i][4 * q + 1] = v.y;
                a[i][4 * q + 2] = v.z; a[i][4 * q + 3] = v.w;
            }
        }
#pragma unroll
        for (int k = 0; k < FE; k++) {
            a01[k] = pk2(a[0][k], a[1][k]);
            a23[k] = pk2(a[2][k], a[3][k]);
        }
    }
    atomicAdd(&g_cnt[col[e0]], 1);
    atomicAdd(&g_cnt[col[e0 + 1]], 1);
    atomicAdd(&g_cnt[col[e0 + 2]], 1);
    atomicAdd(&g_cnt[col[e0 + 3]], 1);

    float wacc[4][8];
#pragma unroll
    for (int i = 0; i < 4; i++) wacc[i][7] = 0.f;

#pragma unroll 1
    for (int l = 0; l < NLAY; l++) {
        const float2* w1l = sw1 + l * 256;
        const float*  b1l = sb1 + l * 16;
        const float*  w2l = sw2 + l * 16;
        float bias2 = sb2[l];
        float s0 = bias2, s1 = bias2, s2 = bias2, s3 = bias2;
#pragma unroll
        for (int j = 0; j < FE; j++) {
            float bj = b1l[j];
            unsigned long long h01 = pk2(bj, bj);
            unsigned long long h23 = h01;
            const ulonglong2* wrow = (const ulonglong2*)(w1l + j * 16);
#pragma unroll
            for (int k = 0; k < FE; k += 2) {
                ulonglong2 w = wrow[k >> 1];
                h01 = fma2(a01[k], w.x, h01);
                h23 = fma2(a23[k], w.x, h23);
                h01 = fma2(a01[k + 1], w.y, h01);
                h23 = fma2(a23[k + 1], w.y, h23);
            }
            float h0, h1, h2, h3;
            upk2(h0, h1, h01); upk2(h2, h3, h23);
            float w2j = w2l[j];
            s0 = fmaf(fmaxf(h0, 0.f), w2j, s0);
            s1 = fmaf(fmaxf(h1, 0.f), w2j, s1);
            s2 = fmaf(fmaxf(h2, 0.f), w2j, s2);
            s3 = fmaf(fmaxf(h3, 0.f), w2j, s3);
        }
        wacc[0][l] = __fdividef(1.f, 1.f + __expf(-s0));
        wacc[1][l] = __fdividef(1.f, 1.f + __expf(-s1));
        wacc[2][l] = __fdividef(1.f, 1.f + __expf(-s2));
        wacc[3][l] = __fdividef(1.f, 1.f + __expf(-s3));
    }
#pragma unroll
    for (int i = 0; i < 4; i++) {
        float4* o = (float4*)&g_w8[(size_t)(e0 + i) * 8];
        o[0] = make_float4(wacc[i][0], wacc[i][1], wacc[i][2], wacc[i][3]);
        o[1] = make_float4(wacc[i][4], wacc[i][5], wacc[i][6], wacc[i][7]);
    }
}

// ---------------- CSR offsets ----------------
__global__ void k_scan() {
    __shared__ int sums[1024];
    const int CH = (NN + 1023) / 1024;
    int t = threadIdx.x;
    int base = t * CH;
    int s = 0;
    for (int i = 0; i < CH; i++) {
        int idx = base + i;
        if (idx < NN) s += g_cnt[idx];
    }
    sums[t] = s;
    __syncthreads();
    for (int off = 1; off < 1024; off <<= 1) {
        int v = 0;
        if (t >= off) v = sums[t - off];
        __syncthreads();
        sums[t] += v;
        __syncthreads();
    }
    int excl = (t == 0) ? 0 : sums[t - 1];
    for (int i = 0; i < CH; i++) {
        int idx = base + i;
        if (idx < NN) {
            int c = g_cnt[idx];
            g_off[idx] = excl;
            excl += c;
        }
    }
    if (t == 1023) g_off[NN] = excl;
}

// ---------------- CSR fill: permute (src, w8) into CSR order ----------------
__global__ void k_fill(const int* __restrict__ row, const int* __restrict__ col) {
    int e = blockIdx.x * blockDim.x + threadIdx.x;
    if (e >= EE) return;
    int r = row[e], c = col[e];
    int p = g_off[c] + atomicAdd(&g_cnt2[c], 1);
    g_srcw[p] = r;
    const float4* wi = (const float4*)&g_w8[(size_t)e * 8];
    float4* wo = (float4*)&g_wcsr[(size_t)p * 8];
    wo[0] = wi[0];
    wo[1] = wi[1];
}

// ---------------- degree: warp/node, coalesced sum of wcsr over range ----------------
__global__ void __launch_bounds__(256) k_deg() {
    int t = threadIdx.x;
    int w = t >> 5, lane = t & 31;
    int node = blockIdx.x * 8 + w;
    int s0 = g_off[node], e0 = g_off[node + 1];
    float s[8];
#pragma unroll
    for (int i = 0; i < 8; i++) s[i] = 0.f;
    for (int p = s0 + lane; p < e0; p += 32) {
        const float4* wp = (const float4*)&g_wcsr[(size_t)p * 8];
        float4 a = wp[0], b = wp[1];
        s[0] += a.x; s[1] += a.y; s[2] += a.z; s[3] += a.w;
        s[4] += b.x; s[5] += b.y; s[6] += b.z;
    }
#pragma unroll
    for (int off = 16; off > 0; off >>= 1) {
#pragma unroll
        for (int i = 0; i < 7; i++)
            s[i] += __shfl_down_sync(0xffffffffu, s[i], off);
    }
    if (lane == 0) {
        float4 d0, d1;
        d0.x = rsqrtf(s[0] + 1.f); d0.y = rsqrtf(s[1] + 1.f);
        d0.z = rsqrtf(s[2] + 1.f); d0.w = rsqrtf(s[3] + 1.f);
        d1.x = rsqrtf(s[4] + 1.f); d1.y = rsqrtf(s[5] + 1.f);
        d1.z = rsqrtf(s[6] + 1.f); d1.w = 0.f;
        float4* o = (float4*)&g_dis2[node * 8];
        o[0] = d0; o[1] = d1;
    }
}

// ---------------- norm: warp/node, coalesced epk writes ----------------
__global__ void __launch_bounds__(256) k_norm() {
    int t = threadIdx.x;
    int w = t >> 5, lane = t & 31;
    int node = blockIdx.x * 8 + w;
    const float4* dd = (const float4*)&g_dis2[node * 8];
    float4 dd0 = dd[0], dd1 = dd[1];
    float dn[7] = {dd0.x, dd0.y, dd0.z, dd0.w, dd1.x, dd1.y, dd1.z};
    int s0 = g_off[node], e0 = g_off[node + 1];
    for (int p = s0 + lane; p < e0; p += 32) {
        int src = g_srcw[p];
        const float4* ds = (const float4*)&g_dis2[src * 8];
        float4 ds0 = ds[0], ds1 = ds[1];
        float sn[7] = {ds0.x, ds0.y, ds0.z, ds0.w, ds1.x, ds1.y, ds1.z};
        const float4* wp = (const float4*)&g_wcsr[(size_t)p * 8];
        float4 wa = wp[0], wb = wp[1];
        float wv[7] = {wa.x, wa.y, wa.z, wa.w, wb.x, wb.y, wb.z};
#pragma unroll
        for (int l = 0; l < NLAY; l++)
            g_epk[(size_t)l * EE + p] = make_int2(src, __float_as_int(sn[l] * wv[l] * dn[l]));
    }
}

// ---------------- node GEMM: 128x64 tile, conflict-free, fp16 out (round-10) ----------------
#define SX_STRIDE  68
#define GEMM_SMEM  ((128 * SX_STRIDE + 64 * SX_STRIDE) * 4)

__global__ void __launch_bounds__(128) k_gemm(const float* __restrict__ x,
                                              const float* __restrict__ lw,
                                              __half* __restrict__ outh,
                                              const double* __restrict__ bns) {
    extern __shared__ __align__(16) float dsm[];
    float (*sx)[SX_STRIDE]  = (float(*)[SX_STRIDE])dsm;                      // [row][k]
    float (*swt)[SX_STRIDE] = (float(*)[SX_STRIDE])(dsm + 128 * SX_STRIDE);  // [k][c]
    __shared__ float smu[CC], sinv[CC];
    int t = threadIdx.x;
#pragma unroll
    for (int i = 0; i < 32; i++) {
        int e = i * 128 + t;
        int c = e >> 6, k = e & 63;
        swt[k][c] = lw[e];
    }
    if (bns != nullptr && t < CC) {
        double s = 0.0, q = 0.0;
#pragma unroll
        for (int cp = 0; cp < 8; cp++) {
            s += bns[cp * 128 + t];
            q += bns[cp * 128 + 64 + t];
        }
        double mu = s * (1.0 / NN);
        double var = q * (1.0 / NN) - mu * mu;
        smu[t] = (float)mu;
        sinv[t] = rsqrtf((float)var + EPSV);
    }
    __syncthreads();
    int row0 = blockIdx.x * 128;
#pragma unroll
    for (int i = 0; i < 16; i++) {
        int idx = i * 128 + t;
        int r = idx >> 4, kq = (idx & 15) * 4;
        int gr = row0 + r;
        float4 v = (gr < NN) ? *(const float4*)&x[gr * CC + kq]
                             : make_float4(0.f, 0.f, 0.f, 0.f);
        if (bns != nullptr) {
            v.x = fmaxf((v.x - smu[kq + 0]) * sinv[kq + 0], 0.f);
            v.y = fmaxf((v.y - smu[kq + 1]) * sinv[kq + 1], 0.f);
            v.z = fmaxf((v.z - smu[kq + 2]) * sinv[kq + 2], 0.f);
            v.w = fmaxf((v.w - smu[kq + 3]) * sinv[kq + 3], 0.f);
        }
        *(float4*)&sx[r][kq] = v;
    }
    __syncthreads();

    int rg = t >> 3;          // rows rg + 16*i, i = 0..7
    int cg = (t & 7) * 4;     // cols cg..cg+3 and cg+32..cg+35
    float acc[8][8];
#pragma unroll
    for (int i = 0; i < 8; i++)
#pragma unroll
        for (int j = 0; j < 8; j++) acc[i][j] = 0.f;

#pragma unroll 1
    for (int kb = 0; kb < CC; kb += 4) {
        float4 a[8];
#pragma unroll
        for (int i = 0; i < 8; i++) a[i] = *(const float4*)&sx[rg + 16 * i][kb];
        float4 b0[4], b1[4];
#pragma unroll
        for (int j = 0; j < 4; j++) {
            b0[j] = *(const float4*)&swt[kb + j][cg];
            b1[j] = *(const float4*)&swt[kb + j][cg + 32];
        }
#pragma unroll
        for (int i = 0; i < 8; i++) {
            float av[4] = {a[i].x, a[i].y, a[i].z, a[i].w};
#pragma unroll
            for (int j = 0; j < 4; j++) {
                acc[i][0] = fmaf(av[j], b0[j].x, acc[i][0]);
                acc[i][1] = fmaf(av[j], b0[j].y, acc[i][1]);
                acc[i][2] = fmaf(av[j], b0[j].z, acc[i][2]);
                acc[i][3] = fmaf(av[j], b0[j].w, acc[i][3]);
                acc[i][4] = fmaf(av[j], b1[j].x, acc[i][4]);
                acc[i][5] = fmaf(av[j], b1[j].y, acc[i][5]);
                acc[i][6] = fmaf(av[j], b1[j].z, acc[i][6]);
                acc[i][7] = fmaf(av[j], b1[j].w, acc[i][7]);
            }
        }
    }
#pragma unroll
    for (int i = 0; i < 8; i++) {
        int gr = row0 + rg + 16 * i;
        if (gr < NN) {
            uint2 s0, s1;
            *(__half2*)&s0.x = __floats2half2_rn(acc[i][0], acc[i][1]);
            *(__half2*)&s0.y = __floats2half2_rn(acc[i][2], acc[i][3]);
            *(__half2*)&s1.x = __floats2half2_rn(acc[i][4], acc[i][5]);
            *(__half2*)&s1.y = __floats2half2_rn(acc[i][6], acc[i][7]);
            *(uint2*)&outh[gr * CC + cg] = s0;
            *(uint2*)&outh[gr * CC + cg + 32] = s1;
        }
    }
}

// ---------------- message gather: warp/node, 256-thr blocks, fp16 rows ----------------
__global__ void __launch_bounds__(256) k_gather(
    int l, const __half2* __restrict__ xh, float* __restrict__ out,
    const float* __restrict__ skipA, const float* __restrict__ skipB,
    const int* __restrict__ batch, int mode, int statslot)
{
    __shared__ __align__(16) int2 sed[8][32];
    __shared__ float ssum[8][64];
    __shared__ float ssq[8][64];
    int t = threadIdx.x;
    int w = t >> 5, lane = t & 31;
    int node = blockIdx.x * 8 + w;

    int s0 = g_off[node], e0 = g_off[node + 1];
    const int2* ep = g_epk + (size_t)l * EE;
    int idx0 = s0 + lane;
    int2 p0 = (idx0 < e0) ? ep[idx0] : make_int2(0, 0);

    float d = g_dis2[node * 8 + l];
    float dd = d * d;
    float2 self = __half22float2(xh[node * 32 + lane]);
    float ax = self.x * dd, ay = self.y * dd;

    for (int j0 = s0; j0 < e0; j0 += 32) {
        int2 p = p0;
        sed[w][lane] = p;
        __syncwarp();
        int idxn = j0 + 32 + lane;
        p0 = (idxn < e0) ? ep[idxn] : make_int2(0, 0);
        int cnt = e0 - j0; if (cnt > 32) cnt = 32;
        int cntp = (cnt + 7) & ~7;
        for (int k = 0; k < cntp; k += 8) {
            int4 q0 = *(const int4*)&sed[w][k];
            int4 q1 = *(const int4*)&sed[w][k + 2];
            int4 q2 = *(const int4*)&sed[w][k + 4];
            int4 q3 = *(const int4*)&sed[w][k + 6];
            __half2 h0 = xh[(size_t)q0.x * 32 + lane];
            __half2 h1 = xh[(size_t)q0.z * 32 + lane];
            __half2 h2 = xh[(size_t)q1.x * 32 + lane];
            __half2 h3 = xh[(size_t)q1.z * 32 + lane];
            __half2 h4 = xh[(size_t)q2.x * 32 + lane];
            __half2 h5 = xh[(size_t)q2.z * 32 + lane];
            __half2 h6 = xh[(size_t)q3.x * 32 + lane];
            __half2 h7 = xh[(size_t)q3.z * 32 + lane];
            float n0 = __int_as_float(q0.y), n1 = __int_as_float(q0.w);
            float n2 = __int_as_float(q1.y), n3 = __int_as_float(q1.w);
            float n4 = __int_as_float(q2.y), n5 = __int_as_float(q2.w);
            float n6 = __int_as_float(q3.y), n7 = __int_as_float(q3.w);
            float2 v0 = __half22float2(h0);
            float2 v1 = __half22float2(h1);
            float2 v2 = __half22float2(h2);
            float2 v3 = __half22float2(h3);
            float2 v4 = __half22float2(h4);
            float2 v5 = __half22float2(h5);
            float2 v6 = __half22float2(h6);
            float2 v7 = __half22float2(h7);
            ax = fmaf(v0.x, n0, ax); ay = fmaf(v0.y, n0, ay);
            ax = fmaf(v1.x, n1, ax); ay = fmaf(v1.y, n1, ay);
            ax = fmaf(v2.x, n2, ax); ay = fmaf(v2.y, n2, ay);
            ax = fmaf(v3.x, n3, ax); ay = fmaf(v3.y, n3, ay);
            ax = fmaf(v4.x, n4, ax); ay = fmaf(v4.y, n4, ay);
            ax = fmaf(v5.x, n5, ax); ay = fmaf(v5.y, n5, ay);
            ax = fmaf(v6.x, n6, ax); ay = fmaf(v6.y, n6, ay);
            ax = fmaf(v7.x, n7, ax); ay = fmaf(v7.y, n7, ay);
        }
        __syncwarp();
    }

    int base = node * 64 + lane * 2;
    float vx = ax, vy = ay;
    if (mode == 1) { vx += skipA[base]; vy += skipA[base + 1]; }
    if (mode == 2) {
        vx = fmaxf(ax + skipA[base] + skipB[base], 0.f);
        vy = fmaxf(ay + skipA[base + 1] + skipB[base + 1], 0.f);
        int g = batch[node];
        atomicMax(&g_pool[g * CC + lane * 2], __float_as_uint(vx));
        atomicMax(&g_pool[g * CC + lane * 2 + 1], __float_as_uint(vy));
    } else {
        float2 o; o.x = vx; o.y = vy;
        ((float2*)out)[node * 32 + lane] = o;
    }

    if (statslot >= 0) {
        ssum[w][lane * 2] = vx; ssum[w][lane * 2 + 1] = vy;
        ssq[w][lane * 2] = vx * vx; ssq[w][lane * 2 + 1] = vy * vy;
        __syncthreads();
        if (t < 64) {
            float s = 0.f, q = 0.f;
#pragma unroll
            for (int ww = 0; ww < 8; ww++) { s += ssum[ww][t]; q += ssq[ww][t]; }
            double* slot = g_bn + statslot * 1024 + (blockIdx.x & 7) * 128;
            atomicAdd(&slot[t], (double)s);
            atomicAdd(&slot[64 + t], (double)q);
        }
    }
}

// ---------------- final linear ----------------
__global__ void k_fin(const float* __restrict__ lw, const float* __restrict__ lb,
                      float* __restrict__ out) {
    __shared__ float sw[NCLSV * CC];
    __shared__ float sb[NCLSV];
    int t = threadIdx.x;
    for (int i = t; i < NCLSV * CC; i += blockDim.x) sw[i] = lw[i];
    if (t < NCLSV) sb[t] = lb[t];
    __syncthreads();
    int g = blockIdx.x * blockDim.x + t;
    if (g >= GG) return;
    float acc[NCLSV];
#pragma unroll
    for (int j = 0; j < NCLSV; j++) acc[j] = sb[j];
    for (int k = 0; k < CC; k++) {
        float p = __uint_as_float(g_pool[g * CC + k]);
#pragma unroll
        for (int j = 0; j < NCLSV; j++) acc[j] += p * sw[j * CC + k];
    }
#pragma unroll
    for (int j = 0; j < NCLSV; j++) out[g * NCLSV + j] = acc[j];
}

// ---------------- host launcher ----------------
extern "C" void kernel_launch(void* const* d_in, const int* in_sizes, int n_in,
                              void* d_out, int out_size) {
    const float* x      = (const float*)d_in[0];
    const int*   ei     = (const int*)d_in[1];
    const int*   batch  = (const int*)d_in[2];
    const float* ea     = (const float*)d_in[4];
    const float* c1_lw  = (const float*)d_in[5];
    const float* c1_w1  = (const float*)d_in[6];
    const float* c1_b1  = (const float*)d_in[7];
    const float* c1_w2  = (const float*)d_in[8];
    const float* c1_b2  = (const float*)d_in[9];
    const float* h1_lw  = (const float*)d_in[10];
    const float* h1_w1  = (const float*)d_in[11];
    const float* h1_b1  = (const float*)d_in[12];
    const float* h1_w2  = (const float*)d_in[13];
    const float* h1_b2  = (const float*)d_in[14];
    const float* h2_lw  = (const float*)d_in[15];
    const float* h2_w1  = (const float*)d_in[16];
    const float* h2_b1  = (const float*)d_in[17];
    const float* h2_w2  = (const float*)d_in[18];
    const float* h2_b2  = (const float*)d_in[19];
    const float* lin_w  = (const float*)d_in[20];
    const float* lin_b  = (const float*)d_in[21];

    const int* row = ei;
    const int* col = ei + EE;

    float *A, *B, *C, *D;
    __half* XLH;
    double* BN;
    cudaGetSymbolAddress((void**)&A,   g_bufA);
    cudaGetSymbolAddress((void**)&B,   g_bufB);
    cudaGetSymbolAddress((void**)&C,   g_bufC);
    cudaGetSymbolAddress((void**)&D,   g_bufD);
    cudaGetSymbolAddress((void**)&XLH, g_xlh);
    cudaGetSymbolAddress((void**)&BN,  g_bn);

    cudaFuncSetAttribute(k_gemm, cudaFuncAttributeMaxDynamicSharedMemorySize, GEMM_SMEM);

    const int EB  = (EE + 255) / 256;             // 3125
    const int EB4 = (EE / 4 + 255) / 256;         // 782
    const int ZB  = (NN * 8 + 255) / 256;         // 1563

    MlpAll mp;
    mp.p[0] = {c1_w1, c1_b1, c1_w2, c1_b2};
    for (int i = 0; i < 3; i++) {
        mp.p[1 + i] = {h1_w1 + i * FE * FE, h1_b1 + i * FE, h1_w2 + i * FE, h1_b2 + i};
        mp.p[4 + i] = {h2_w1 + i * FE * FE, h2_b1 + i * FE, h2_w2 + i * FE, h2_b2 + i};
    }

    const int GEMM_B = (NN + 127) / 128;  // 391
    const int GATH_B = NN / 8;            // 6250

    k_zero<<<ZB, 256>>>();                                        // 0
    k_mlp<<<EB4, 256>>>(ea, col, mp);                             // 1
    k_scan<<<1, 1024>>>();                                        // 2
    k_gemm<<<GEMM_B, 128, GEMM_SMEM>>>(x, c1_lw, XLH, nullptr);   // 3  <- profiled slot
    k_fill<<<EB, 256>>>(row, col);                                // 4
    k_deg<<<GATH_B, 256>>>();                                     // 5
    k_norm<<<GATH_B, 256>>>();                                    // 6

    k_gather<<<GATH_B, 256>>>(0, (const __half2*)XLH, A, nullptr, nullptr, nullptr, 0, 0);
    k_gemm<<<GEMM_B, 128, GEMM_SMEM>>>(A, h1_lw + 0 * CC * CC, XLH, BN + 0 * 1024);
    k_gather<<<GATH_B, 256>>>(1, (const __half2*)XLH, B, nullptr, nullptr, nullptr, 0, 1);
    k_gemm<<<GEMM_B, 128, GEMM_SMEM>>>(B, h1_lw + 1 * CC * CC, XLH, BN + 1 * 1024);
    k_gather<<<GATH_B, 256>>>(2, (const __half2*)XLH, C, nullptr, nullptr, nullptr, 0, 2);
    k_gemm<<<GEMM_B, 128, GEMM_SMEM>>>(C, h1_lw + 2 * CC * CC, XLH, BN + 2 * 1024);
    k_gather<<<GATH_B, 256>>>(3, (const __half2*)XLH, D, A, nullptr, nullptr, 1, 3);   // D = x1
    k_gemm<<<GEMM_B, 128, GEMM_SMEM>>>(D, h2_lw + 0 * CC * CC, XLH, BN + 3 * 1024);
    k_gather<<<GATH_B, 256>>>(4, (const __half2*)XLH, B, nullptr, nullptr, nullptr, 0, 4);
    k_gemm<<<GEMM_B, 128, GEMM_SMEM>>>(B, h2_lw + 1 * CC * CC, XLH, BN + 4 * 1024);
    k_gather<<<GATH_B, 256>>>(5, (const __half2*)XLH, C, nullptr, nullptr, nullptr, 0, 5);
    k_gemm<<<GEMM_B, 128, GEMM_SMEM>>>(C, h2_lw + 2 * CC * CC, XLH, BN + 5 * 1024);
    k_gather<<<GATH_B, 256>>>(6, (const __half2*)XLH, nullptr, A, D, batch, 2, -1);    // pool
    k_fin<<<2, 256>>>(lin_w, lin_b, (float*)d_out);
}